// round 2
// baseline (speedup 1.0000x reference)
#include <cuda_runtime.h>
#include <math.h>

// ---------------------------------------------------------------------------
// PhysicsGuidedAttentionCorrected — fp32 via packed f32x2 (FFMA2) pipe
// B=8, N=1024, C=256, NUM_HEADS=8, hd=32
// ---------------------------------------------------------------------------

#define B_ 8
#define N_ 1024
#define C_ 256
#define NH_ 8
#define HD_ 32

typedef unsigned long long ull;

__device__ __forceinline__ ull pk2(float lo, float hi) {
    ull r;
    asm("mov.b64 %0, {%1,%2};" : "=l"(r) : "f"(lo), "f"(hi));
    return r;
}
__device__ __forceinline__ void upk2(ull v, float& lo, float& hi) {
    asm("mov.b64 {%0,%1}, %2;" : "=f"(lo), "=f"(hi) : "l"(v));
}
__device__ __forceinline__ void fma2(ull& d, ull a, ull b) {
    asm("fma.rn.f32x2 %0, %1, %2, %3;" : "=l"(d) : "l"(a), "l"(b), "l"(d));
}
__device__ __forceinline__ void mul2(ull& d, ull a) {
    asm("mul.rn.f32x2 %0, %1, %2;" : "=l"(d) : "l"(d), "l"(a));
}
__device__ __forceinline__ void add2(ull& d, ull a) {
    asm("add.rn.f32x2 %0, %1, %2;" : "=l"(d) : "l"(d), "l"(a));
}

// scratch (device globals; no allocations allowed)
__device__ float g_qkv[B_ * N_ * 3 * C_];
__device__ float g_attn[B_ * N_ * C_];
__device__ float g_ws[B_ * N_];

// ---------------------------------------------------------------------------
// wind strength
// ---------------------------------------------------------------------------
__global__ void wind_kernel(const float* __restrict__ u,
                            const float* __restrict__ v,
                            float* __restrict__ ws) {
    int t = blockIdx.x * blockDim.x + threadIdx.x;
    if (t >= B_ * N_) return;
    int b = t >> 10;
    int n = t & 1023;
    int r = n >> 5;
    int c = n & 31;
    const float* ub = u + b * 4096;
    const float* vb = v + b * 4096;
    float s = 0.0f;
#pragma unroll
    for (int dr = 0; dr < 2; ++dr)
#pragma unroll
        for (int dc = 0; dc < 2; ++dc) {
            int idx = (2 * r + dr) * 64 + (2 * c + dc);
            float uu = ub[idx], vv = vb[idx];
            s += sqrtf(uu * uu + vv * vv + 1e-8f);
        }
    ws[t] = s * 0.25f;
}

// ---------------------------------------------------------------------------
// SGEMM: C[m,n] = sum_k A[m,k]*B[n,k] (+bias[n]); FFMA2 inner product.
// 128x128 tile, BK=16, 256 threads, 8x8 per thread (4 c-pairs).
// A duplicated in smem so LDS delivers (a,a) packed pairs.
// ---------------------------------------------------------------------------
template <bool HAS_BIAS>
__global__ __launch_bounds__(256, 2)
void gemm_abt(const float* __restrict__ A, const float* __restrict__ B,
              const float* __restrict__ bias, float* __restrict__ C,
              int M, int N, int K) {
    __shared__ __align__(16) float Asd[16][264];   // dup: [k][2*row]
    __shared__ __align__(16) float Bs[16][132];

    const int tid = threadIdx.x;
    const int tx = tid & 15;
    const int ty = tid >> 4;
    const int bx = blockIdx.x;
    const int by = blockIdx.y;

    const float* Ag = A + (size_t)by * 128 * K;
    const float* Bg = B + (size_t)bx * 128 * K;

    ull accp[8][4];
#pragma unroll
    for (int r = 0; r < 8; ++r)
#pragma unroll
        for (int cp = 0; cp < 4; ++cp) accp[r][cp] = 0ull;

    const int lrow = tid >> 2;
    const int lk = (tid & 3) * 4;

    for (int kb = 0; kb < K; kb += 16) {
#pragma unroll
        for (int h = 0; h < 2; ++h) {
            int row = lrow + h * 64;
            float4 a = *reinterpret_cast<const float4*>(Ag + (size_t)row * K + kb + lk);
            *reinterpret_cast<ull*>(&Asd[lk + 0][2 * row]) = pk2(a.x, a.x);
            *reinterpret_cast<ull*>(&Asd[lk + 1][2 * row]) = pk2(a.y, a.y);
            *reinterpret_cast<ull*>(&Asd[lk + 2][2 * row]) = pk2(a.z, a.z);
            *reinterpret_cast<ull*>(&Asd[lk + 3][2 * row]) = pk2(a.w, a.w);
            float4 b = *reinterpret_cast<const float4*>(Bg + (size_t)row * K + kb + lk);
            Bs[lk + 0][row] = b.x; Bs[lk + 1][row] = b.y;
            Bs[lk + 2][row] = b.z; Bs[lk + 3][row] = b.w;
        }
        __syncthreads();

#pragma unroll 4
        for (int k = 0; k < 16; ++k) {
            ulonglong2 a0 = *reinterpret_cast<const ulonglong2*>(&Asd[k][16 * ty]);
            ulonglong2 a1 = *reinterpret_cast<const ulonglong2*>(&Asd[k][16 * ty + 4]);
            ulonglong2 a2 = *reinterpret_cast<const ulonglong2*>(&Asd[k][16 * ty + 8]);
            ulonglong2 a3 = *reinterpret_cast<const ulonglong2*>(&Asd[k][16 * ty + 12]);
            ulonglong2 b0 = *reinterpret_cast<const ulonglong2*>(&Bs[k][8 * tx]);
            ulonglong2 b1 = *reinterpret_cast<const ulonglong2*>(&Bs[k][8 * tx + 4]);
            ull ad[8] = {a0.x, a0.y, a1.x, a1.y, a2.x, a2.y, a3.x, a3.y};
            ull bp[4] = {b0.x, b0.y, b1.x, b1.y};
#pragma unroll
            for (int r = 0; r < 8; ++r)
#pragma unroll
                for (int cp = 0; cp < 4; ++cp)
                    fma2(accp[r][cp], ad[r], bp[cp]);
        }
        __syncthreads();
    }

    ull bvp[4];
    if (HAS_BIAS) {
        const ulonglong2* bq =
            reinterpret_cast<const ulonglong2*>(bias + bx * 128 + 8 * tx);
        ulonglong2 q0 = bq[0], q1 = bq[1];
        bvp[0] = q0.x; bvp[1] = q0.y; bvp[2] = q1.x; bvp[3] = q1.y;
    }
#pragma unroll
    for (int r = 0; r < 8; ++r) {
        if (HAS_BIAS) {
#pragma unroll
            for (int cp = 0; cp < 4; ++cp) add2(accp[r][cp], bvp[cp]);
        }
        int grow = by * 128 + 8 * ty + r;
        float* Cp = C + (size_t)grow * N + bx * 128 + 8 * tx;
        ulonglong2 o0, o1;
        o0.x = accp[r][0]; o0.y = accp[r][1];
        o1.x = accp[r][2]; o1.y = accp[r][3];
        *reinterpret_cast<ulonglong2*>(Cp) = o0;
        *reinterpret_cast<ulonglong2*>(Cp + 4) = o1;
    }
}

// ---------------------------------------------------------------------------
// fused attention with FFMA2 inner products.
// block = (b, h, 64-query chunk), 256 threads (tx 0..15 key cols, ty 0..15 rows)
// Q and V duplicated in smem; K and P natural.
// dynamic smem: Qsd[32][136] | Ks[32][68] | Vsd[64][72] | Ps[64][68] | e/w[4][64]
// ---------------------------------------------------------------------------
#define ATTN_SMEM_FLOATS (32 * 136 + 32 * 68 + 64 * 72 + 64 * 68 + 4 * 64)

__global__ __launch_bounds__(256)
void attn_kernel(const float* __restrict__ qkv,
                 const float* __restrict__ elev,
                 const float* __restrict__ ws,
                 const float* __restrict__ alpha_p,
                 const float* __restrict__ beta_p,
                 float* __restrict__ outp) {
    extern __shared__ float sm[];
    float (*Qsd)[136] = reinterpret_cast<float(*)[136]>(sm);                 // dup [d][2i]
    float (*Ks)[68]   = reinterpret_cast<float(*)[68]>(sm + 32 * 136);       // [d][j]
    float (*Vsd)[72]  = reinterpret_cast<float(*)[72]>(sm + 32 * 136 + 32 * 68);  // dup [j][2d]
    float (*Ps)[68]   = reinterpret_cast<float(*)[68]>(sm + 32 * 136 + 32 * 68 + 64 * 72);
    float* eQ = sm + 32 * 136 + 32 * 68 + 64 * 72 + 64 * 68;
    float* wQ = eQ + 64;
    float* eK = wQ + 64;
    float* wK = eK + 64;

    const int tid = threadIdx.x;
    const int tx = tid & 15;
    const int ty = tid >> 4;
    const int qc = blockIdx.x;
    const int h  = blockIdx.y;
    const int b  = blockIdx.z;

    const float alpha = *alpha_p;
    const float beta  = *beta_p;
    const float scale = 0.17677669529663687f;   // 1/sqrt(32)

    const int qrow0 = b * N_ + qc * 64;

    // load Q tile duplicated: Qsd[d][2i]=(q,q)
#pragma unroll
    for (int it = 0; it < 2; ++it) {
        int idx = tid + it * 256;
        int i = idx >> 3;
        int dq = (idx & 7) * 4;
        float4 q = *reinterpret_cast<const float4*>(
            qkv + (size_t)(qrow0 + i) * 768 + h * HD_ + dq);
        *reinterpret_cast<ull*>(&Qsd[dq + 0][2 * i]) = pk2(q.x, q.x);
        *reinterpret_cast<ull*>(&Qsd[dq + 1][2 * i]) = pk2(q.y, q.y);
        *reinterpret_cast<ull*>(&Qsd[dq + 2][2 * i]) = pk2(q.z, q.z);
        *reinterpret_cast<ull*>(&Qsd[dq + 3][2 * i]) = pk2(q.w, q.w);
    }
    if (tid < 64) {
        eQ[tid] = elev[qrow0 + tid];
        wQ[tid] = ws[qrow0 + tid];
    }
    __syncthreads();

    float eQr[4], wQr[4];
#pragma unroll
    for (int r = 0; r < 4; ++r) { eQr[r] = eQ[4 * ty + r]; wQr[r] = wQ[4 * ty + r]; }

    float m[4], l[4];
    ull accp[2][2];   // [row-pair][dim]  rows (4ty+0,4ty+1) and (4ty+2,4ty+3)
#pragma unroll
    for (int r = 0; r < 4; ++r) { m[r] = -1e30f; l[r] = 0.0f; }
    accp[0][0] = accp[0][1] = accp[1][0] = accp[1][1] = 0ull;

#pragma unroll 1
    for (int kt = 0; kt < 16; ++kt) {
        __syncthreads();   // protect Ks/Vsd/Ps reuse vs previous iteration reads
        const int krow0 = b * N_ + kt * 64;

        // load K (transposed, natural) and V (duplicated)
#pragma unroll
        for (int it = 0; it < 2; ++it) {
            int idx = tid + it * 256;
            int i = idx >> 3;
            int dq = (idx & 7) * 4;
            size_t base = (size_t)(krow0 + i) * 768 + h * HD_ + dq;
            float4 kv = *reinterpret_cast<const float4*>(qkv + base + 256);
            Ks[dq + 0][i] = kv.x; Ks[dq + 1][i] = kv.y;
            Ks[dq + 2][i] = kv.z; Ks[dq + 3][i] = kv.w;
            float4 vv = *reinterpret_cast<const float4*>(qkv + base + 512);
            *reinterpret_cast<ull*>(&Vsd[i][2 * dq + 0]) = pk2(vv.x, vv.x);
            *reinterpret_cast<ull*>(&Vsd[i][2 * dq + 2]) = pk2(vv.y, vv.y);
            *reinterpret_cast<ull*>(&Vsd[i][2 * dq + 4]) = pk2(vv.z, vv.z);
            *reinterpret_cast<ull*>(&Vsd[i][2 * dq + 6]) = pk2(vv.w, vv.w);
        }
        if (tid < 64) {
            eK[tid] = elev[krow0 + tid];
            wK[tid] = ws[krow0 + tid];
        }
        __syncthreads();

        // S = Q K^T : sp[r][cp] packs (s[r][2cp], s[r][2cp+1])
        ull sp[4][2];
#pragma unroll
        for (int r = 0; r < 4; ++r) { sp[r][0] = 0ull; sp[r][1] = 0ull; }

#pragma unroll 8
        for (int d = 0; d < 32; ++d) {
            ulonglong2 qa = *reinterpret_cast<const ulonglong2*>(&Qsd[d][8 * ty]);
            ulonglong2 qb = *reinterpret_cast<const ulonglong2*>(&Qsd[d][8 * ty + 4]);
            ulonglong2 kp = *reinterpret_cast<const ulonglong2*>(&Ks[d][4 * tx]);
            fma2(sp[0][0], qa.x, kp.x); fma2(sp[0][1], qa.x, kp.y);
            fma2(sp[1][0], qa.y, kp.x); fma2(sp[1][1], qa.y, kp.y);
            fma2(sp[2][0], qb.x, kp.x); fma2(sp[2][1], qb.x, kp.y);
            fma2(sp[3][0], qb.y, kp.x); fma2(sp[3][1], qb.y, kp.y);
        }

        float s[4][4];
#pragma unroll
        for (int r = 0; r < 4; ++r) {
            upk2(sp[r][0], s[r][0], s[r][1]);
            upk2(sp[r][1], s[r][2], s[r][3]);
        }

        // scale + physics bias
        float eKc[4], wKc[4];
#pragma unroll
        for (int c = 0; c < 4; ++c) { eKc[c] = eK[4 * tx + c]; wKc[c] = wK[4 * tx + c]; }
#pragma unroll
        for (int r = 0; r < 4; ++r)
#pragma unroll
            for (int c = 0; c < 4; ++c) {
                float ed = (eKc[c] - eQr[r]) * 1e-3f;
                ed = fmaxf(ed, 0.0f);
                float z = (wQr[r] + wKc[c]) * 0.5f - 5.0f;
                float wf = 1.0f / (1.0f + __expf(-z));
                float bia = -alpha * ed * (1.0f - beta * wf);
                bia = fminf(fmaxf(bia, -10.0f), 0.0f);
                s[r][c] = fmaf(s[r][c], scale, bia);
            }

        // online softmax
        float sc[4];
#pragma unroll
        for (int r = 0; r < 4; ++r) {
            float mt = fmaxf(fmaxf(s[r][0], s[r][1]), fmaxf(s[r][2], s[r][3]));
#pragma unroll
            for (int o = 1; o < 16; o <<= 1)
                mt = fmaxf(mt, __shfl_xor_sync(0xffffffffu, mt, o));
            float mn = fmaxf(m[r], mt);
            sc[r] = __expf(m[r] - mn);
            float rs = 0.0f;
#pragma unroll
            for (int c = 0; c < 4; ++c) {
                float p = __expf(s[r][c] - mn);
                s[r][c] = p;
                rs += p;
            }
#pragma unroll
            for (int o = 1; o < 16; o <<= 1)
                rs += __shfl_xor_sync(0xffffffffu, rs, o);
            l[r] = l[r] * sc[r] + rs;
            m[r] = mn;
        }
        {
            ull scp0 = pk2(sc[0], sc[1]);
            ull scp1 = pk2(sc[2], sc[3]);
            mul2(accp[0][0], scp0); mul2(accp[0][1], scp0);
            mul2(accp[1][0], scp1); mul2(accp[1][1], scp1);
        }

        // P -> smem (transposed: Ps[j][i]), packed row-pair stores
#pragma unroll
        for (int c = 0; c < 4; ++c) {
            *reinterpret_cast<ull*>(&Ps[4 * tx + c][4 * ty + 0]) = pk2(s[0][c], s[1][c]);
            *reinterpret_cast<ull*>(&Ps[4 * tx + c][4 * ty + 2]) = pk2(s[2][c], s[3][c]);
        }
        __syncthreads();

        // O += P @ V : rows as natural pairs from Ps, dims as dup pairs from Vsd
#pragma unroll 8
        for (int j = 0; j < 64; ++j) {
            ulonglong2 pp = *reinterpret_cast<const ulonglong2*>(&Ps[j][4 * ty]);
            ulonglong2 vd = *reinterpret_cast<const ulonglong2*>(&Vsd[j][4 * tx]);
            fma2(accp[0][0], pp.x, vd.x);
            fma2(accp[0][1], pp.x, vd.y);
            fma2(accp[1][0], pp.y, vd.x);
            fma2(accp[1][1], pp.y, vd.y);
        }
    }

    // epilogue
    float inv[4];
#pragma unroll
    for (int r = 0; r < 4; ++r) inv[r] = 1.0f / l[r];
    ull ivp0 = pk2(inv[0], inv[1]);
    ull ivp1 = pk2(inv[2], inv[3]);
    mul2(accp[0][0], ivp0); mul2(accp[0][1], ivp0);
    mul2(accp[1][0], ivp1); mul2(accp[1][1], ivp1);

    float o00, o10, o01, o11, o20, o30, o21, o31;
    upk2(accp[0][0], o00, o10);
    upk2(accp[0][1], o01, o11);
    upk2(accp[1][0], o20, o30);
    upk2(accp[1][1], o21, o31);

    float* op = outp + (size_t)(qrow0 + 4 * ty) * C_ + h * HD_ + 2 * tx;
    *reinterpret_cast<ull*>(op + 0 * C_) = pk2(o00, o01);
    *reinterpret_cast<ull*>(op + 1 * C_) = pk2(o10, o11);
    *reinterpret_cast<ull*>(op + 2 * C_) = pk2(o20, o21);
    *reinterpret_cast<ull*>(op + 3 * C_) = pk2(o30, o31);
}

// ---------------------------------------------------------------------------
// launch
// ---------------------------------------------------------------------------
extern "C" void kernel_launch(void* const* d_in, const int* in_sizes, int n_in,
                              void* d_out, int out_size) {
    const float* x     = (const float*)d_in[0];
    const float* elev  = (const float*)d_in[1];
    const float* uw    = (const float*)d_in[2];
    const float* vw    = (const float*)d_in[3];
    const float* wqkv  = (const float*)d_in[4];
    const float* wproj = (const float*)d_in[5];
    const float* bproj = (const float*)d_in[6];
    const float* alpha = (const float*)d_in[7];
    const float* beta  = (const float*)d_in[8];
    float* out = (float*)d_out;

    float *qkv_p, *attn_p, *ws_p;
    cudaGetSymbolAddress((void**)&qkv_p, g_qkv);
    cudaGetSymbolAddress((void**)&attn_p, g_attn);
    cudaGetSymbolAddress((void**)&ws_p, g_ws);

    const int attn_smem = ATTN_SMEM_FLOATS * 4;
    cudaFuncSetAttribute(attn_kernel, cudaFuncAttributeMaxDynamicSharedMemorySize,
                         attn_smem);

    wind_kernel<<<32, 256>>>(uw, vw, ws_p);

    gemm_abt<false><<<dim3(768 / 128, 8192 / 128), 256>>>(
        x, wqkv, nullptr, qkv_p, 8192, 768, 256);

    attn_kernel<<<dim3(16, NH_, B_), 256, attn_smem>>>(
        qkv_p, elev, ws_p, alpha, beta, attn_p);

    gemm_abt<true><<<dim3(256 / 128, 8192 / 128), 256>>>(
        attn_p, wproj, bproj, out, 8192, 256, 256);
}

// round 4
// speedup vs baseline: 1.5883x; 1.5883x over previous
#include <cuda_runtime.h>
#include <cuda_bf16.h>
#include <math.h>
#include <cstdint>

// ---------------------------------------------------------------------------
// PhysicsGuidedAttentionCorrected
// B=8, N=1024, C=256, NUM_HEADS=8, hd=32
// R4: GEMMs via legacy warp-level mma.sync bf16 hi/lo split (compute_103-safe);
//     attention = R1 scalar kernel.
// ---------------------------------------------------------------------------

#define B_ 8
#define N_ 1024
#define C_ 256
#define NH_ 8
#define HD_ 32

// scratch (device globals; no allocations allowed)
__device__ float g_qkv[B_ * N_ * 3 * C_];
__device__ float g_attn[B_ * N_ * C_];
__device__ float g_ws[B_ * N_];

// ---------------------------------------------------------------------------
// helpers
// ---------------------------------------------------------------------------
__device__ __forceinline__ uint32_t smem_u32(const void* p) {
    uint32_t a;
    asm("{ .reg .u64 t; cvta.to.shared.u64 t, %1; cvt.u32.u64 %0, t; }"
        : "=r"(a) : "l"(p));
    return a;
}

#define LDSM_X4(r0, r1, r2, r3, addr)                                        \
    asm volatile("ldmatrix.sync.aligned.m8n8.x4.shared.b16 {%0,%1,%2,%3}, [%4];" \
                 : "=r"(r0), "=r"(r1), "=r"(r2), "=r"(r3) : "r"(addr))

#define MMA_BF16(d, a0, a1, a2, a3, b0, b1)                                  \
    asm volatile("mma.sync.aligned.m16n8k16.row.col.f32.bf16.bf16.f32 "      \
                 "{%0,%1,%2,%3}, {%4,%5,%6,%7}, {%8,%9}, {%0,%1,%2,%3};"     \
                 : "+f"((d)[0]), "+f"((d)[1]), "+f"((d)[2]), "+f"((d)[3])    \
                 : "r"(a0), "r"(a1), "r"(a2), "r"(a3), "r"(b0), "r"(b1))

__device__ __forceinline__ void split2(float x, float y,
                                       __nv_bfloat162& hi, __nv_bfloat162& lo) {
    __nv_bfloat16 hx = __float2bfloat16_rn(x);
    __nv_bfloat16 hy = __float2bfloat16_rn(y);
    hi = __nv_bfloat162(hx, hy);
    lo = __nv_bfloat162(__float2bfloat16_rn(x - __bfloat162float(hx)),
                        __float2bfloat16_rn(y - __bfloat162float(hy)));
}

// ---------------------------------------------------------------------------
// wind strength
// ---------------------------------------------------------------------------
__global__ void wind_kernel(const float* __restrict__ u,
                            const float* __restrict__ v,
                            float* __restrict__ ws) {
    int t = blockIdx.x * blockDim.x + threadIdx.x;
    if (t >= B_ * N_) return;
    int b = t >> 10;
    int n = t & 1023;
    int r = n >> 5;
    int c = n & 31;
    const float* ub = u + b * 4096;
    const float* vb = v + b * 4096;
    float s = 0.0f;
#pragma unroll
    for (int dr = 0; dr < 2; ++dr)
#pragma unroll
        for (int dc = 0; dc < 2; ++dc) {
            int idx = (2 * r + dr) * 64 + (2 * c + dc);
            float uu = ub[idx], vv = vb[idx];
            s += sqrtf(uu * uu + vv * vv + 1e-8f);
        }
    ws[t] = s * 0.25f;
}

// ---------------------------------------------------------------------------
// bf16-split tensor-core GEMM: C[m,n] = sum_k A[m,k]*B[n,k] (+bias[n])
// K fixed 256. CTA tile 128x128, 8 warps (2M x 4N), warp tile 64x32.
// Terms: AhBh + AhBl + AlBh (fp32 accumulate).
// ---------------------------------------------------------------------------
#define PITCH 40   // bf16 elements per smem row (32 data + 8 pad)

template <bool HAS_BIAS>
__global__ __launch_bounds__(256)
void gemm_mma(const float* __restrict__ A, const float* __restrict__ B,
              const float* __restrict__ bias, float* __restrict__ C, int N) {
    __shared__ __align__(16) __nv_bfloat16 Ah[128 * PITCH];
    __shared__ __align__(16) __nv_bfloat16 Al[128 * PITCH];
    __shared__ __align__(16) __nv_bfloat16 Bh[128 * PITCH];
    __shared__ __align__(16) __nv_bfloat16 Bl[128 * PITCH];

    const int tid = threadIdx.x;
    const int lane = tid & 31;
    const int wid = tid >> 5;
    const int wm = wid & 1;        // 0..1  (M)
    const int wn = wid >> 1;       // 0..3  (N)
    const int bx = blockIdx.x;
    const int by = blockIdx.y;

    const float* Ag = A + (size_t)by * 128 * 256;
    const float* Bg = B + (size_t)bx * 128 * 256;

    float acc[4][4][4];
#pragma unroll
    for (int mt = 0; mt < 4; ++mt)
#pragma unroll
        for (int nt = 0; nt < 4; ++nt)
#pragma unroll
            for (int i = 0; i < 4; ++i) acc[mt][nt][i] = 0.0f;

    // ldmatrix lane-derived addressing
    const int a_row = (lane & 15);
    const int a_ch  = (lane & 16) ? 8 : 0;        // k half for A
    const int b_row = (lane & 7) + ((lane & 16) ? 8 : 0);
    const int b_ch  = (lane & 8) ? 8 : 0;         // k half for B

    const uint32_t sAh = smem_u32(Ah), sAl = smem_u32(Al);
    const uint32_t sBh = smem_u32(Bh), sBl = smem_u32(Bl);

    const uint32_t aoff = (uint32_t)((wm * 64 + a_row) * PITCH + a_ch) * 2;
    const uint32_t boff = (uint32_t)((wn * 32 + b_row) * PITCH + b_ch) * 2;

#pragma unroll 1
    for (int kb = 0; kb < 8; ++kb) {
        __syncthreads();   // previous iter's smem reads done
        // stage: 128 rows x 32 floats per operand -> hi/lo bf16
#pragma unroll
        for (int i = 0; i < 4; ++i) {
            int slot = tid + i * 256;          // 0..1023
            int row = slot >> 3;
            int c4 = (slot & 7) * 4;
            float4 av = *reinterpret_cast<const float4*>(
                Ag + (size_t)row * 256 + kb * 32 + c4);
            __nv_bfloat162 h01, l01, h23, l23;
            split2(av.x, av.y, h01, l01);
            split2(av.z, av.w, h23, l23);
            *reinterpret_cast<__nv_bfloat162*>(&Ah[row * PITCH + c4])     = h01;
            *reinterpret_cast<__nv_bfloat162*>(&Ah[row * PITCH + c4 + 2]) = h23;
            *reinterpret_cast<__nv_bfloat162*>(&Al[row * PITCH + c4])     = l01;
            *reinterpret_cast<__nv_bfloat162*>(&Al[row * PITCH + c4 + 2]) = l23;
            float4 bv = *reinterpret_cast<const float4*>(
                Bg + (size_t)row * 256 + kb * 32 + c4);
            split2(bv.x, bv.y, h01, l01);
            split2(bv.z, bv.w, h23, l23);
            *reinterpret_cast<__nv_bfloat162*>(&Bh[row * PITCH + c4])     = h01;
            *reinterpret_cast<__nv_bfloat162*>(&Bh[row * PITCH + c4 + 2]) = h23;
            *reinterpret_cast<__nv_bfloat162*>(&Bl[row * PITCH + c4])     = l01;
            *reinterpret_cast<__nv_bfloat162*>(&Bl[row * PITCH + c4 + 2]) = l23;
        }
        __syncthreads();

#pragma unroll
        for (int kk = 0; kk < 2; ++kk) {
            const uint32_t kof = (uint32_t)(kk * 16) * 2;

            // B fragments: 2 ldmatrix.x4 per buffer cover 4 n-tiles
            uint32_t bhf[2][4], blf[2][4];
#pragma unroll
            for (int ntp = 0; ntp < 2; ++ntp) {
                uint32_t ba = boff + (uint32_t)(ntp * 16 * PITCH) * 2 + kof;
                LDSM_X4(bhf[ntp][0], bhf[ntp][1], bhf[ntp][2], bhf[ntp][3], sBh + ba);
                LDSM_X4(blf[ntp][0], blf[ntp][1], blf[ntp][2], blf[ntp][3], sBl + ba);
            }

#pragma unroll
            for (int mt = 0; mt < 4; ++mt) {
                uint32_t aa = aoff + (uint32_t)(mt * 16 * PITCH) * 2 + kof;
                uint32_t ah0, ah1, ah2, ah3, al0, al1, al2, al3;
                LDSM_X4(ah0, ah1, ah2, ah3, sAh + aa);
                LDSM_X4(al0, al1, al2, al3, sAl + aa);
#pragma unroll
                for (int nt = 0; nt < 4; ++nt) {
                    const int ntp = nt >> 1;
                    const int hb = (nt & 1) * 2;
                    MMA_BF16(acc[mt][nt], ah0, ah1, ah2, ah3,
                             bhf[ntp][hb], bhf[ntp][hb + 1]);
                    MMA_BF16(acc[mt][nt], ah0, ah1, ah2, ah3,
                             blf[ntp][hb], blf[ntp][hb + 1]);
                    MMA_BF16(acc[mt][nt], al0, al1, al2, al3,
                             bhf[ntp][hb], bhf[ntp][hb + 1]);
                }
            }
        }
    }

    // epilogue
    const int gid = lane >> 2;
    const int tig = lane & 3;
#pragma unroll
    for (int mt = 0; mt < 4; ++mt) {
        int row = by * 128 + wm * 64 + mt * 16 + gid;
#pragma unroll
        for (int nt = 0; nt < 4; ++nt) {
            int col = bx * 128 + wn * 32 + nt * 8 + 2 * tig;
            float2 v0 = make_float2(acc[mt][nt][0], acc[mt][nt][1]);
            float2 v1 = make_float2(acc[mt][nt][2], acc[mt][nt][3]);
            if (HAS_BIAS) {
                float2 bb = *reinterpret_cast<const float2*>(bias + col);
                v0.x += bb.x; v0.y += bb.y;
                v1.x += bb.x; v1.y += bb.y;
            }
            *reinterpret_cast<float2*>(C + (size_t)row * N + col) = v0;
            *reinterpret_cast<float2*>(C + (size_t)(row + 8) * N + col) = v1;
        }
    }
}

// ---------------------------------------------------------------------------
// fused attention (R1 scalar version — known good)
// ---------------------------------------------------------------------------
__global__ __launch_bounds__(256)
void attn_kernel(const float* __restrict__ qkv,
                 const float* __restrict__ elev,
                 const float* __restrict__ ws,
                 const float* __restrict__ alpha_p,
                 const float* __restrict__ beta_p,
                 float* __restrict__ outp) {
    __shared__ __align__(16) float Qs[32][68];
    __shared__ __align__(16) float Ks[32][68];
    __shared__ __align__(16) float Vs[64][36];
    __shared__ __align__(16) float Ps[64][68];
    __shared__ float eQ[64], wQ[64], eK[64], wK[64];

    const int tid = threadIdx.x;
    const int tx = tid & 15;
    const int ty = tid >> 4;
    const int qc = blockIdx.x;
    const int h  = blockIdx.y;
    const int b  = blockIdx.z;

    const float alpha = *alpha_p;
    const float beta  = *beta_p;
    const float scale = 0.17677669529663687f;

    const int qrow0 = b * N_ + qc * 64;

#pragma unroll
    for (int it = 0; it < 2; ++it) {
        int idx = tid + it * 256;
        int i = idx >> 3;
        int dq = (idx & 7) * 4;
        float4 q = *reinterpret_cast<const float4*>(
            qkv + (size_t)(qrow0 + i) * 768 + h * HD_ + dq);
        Qs[dq + 0][i] = q.x; Qs[dq + 1][i] = q.y;
        Qs[dq + 2][i] = q.z; Qs[dq + 3][i] = q.w;
    }
    if (tid < 64) {
        eQ[tid] = elev[qrow0 + tid];
        wQ[tid] = ws[qrow0 + tid];
    }
    __syncthreads();

    float eQr[4], wQr[4];
#pragma unroll
    for (int r = 0; r < 4; ++r) { eQr[r] = eQ[4 * ty + r]; wQr[r] = wQ[4 * ty + r]; }

    float m[4], l[4], acc[4][2];
#pragma unroll
    for (int r = 0; r < 4; ++r) {
        m[r] = -1e30f; l[r] = 0.0f; acc[r][0] = 0.0f; acc[r][1] = 0.0f;
    }

#pragma unroll 1
    for (int kt = 0; kt < 16; ++kt) {
        __syncthreads();
        const int krow0 = b * N_ + kt * 64;

#pragma unroll
        for (int it = 0; it < 2; ++it) {
            int idx = tid + it * 256;
            int i = idx >> 3;
            int dq = (idx & 7) * 4;
            size_t base = (size_t)(krow0 + i) * 768 + h * HD_ + dq;
            float4 kv = *reinterpret_cast<const float4*>(qkv + base + 256);
            Ks[dq + 0][i] = kv.x; Ks[dq + 1][i] = kv.y;
            Ks[dq + 2][i] = kv.z; Ks[dq + 3][i] = kv.w;
            float4 vv = *reinterpret_cast<const float4*>(qkv + base + 512);
            *reinterpret_cast<float4*>(&Vs[i][dq]) = vv;
        }
        if (tid < 64) {
            eK[tid] = elev[krow0 + tid];
            wK[tid] = ws[krow0 + tid];
        }
        __syncthreads();

        float s[4][4];
#pragma unroll
        for (int r = 0; r < 4; ++r)
#pragma unroll
            for (int c = 0; c < 4; ++c) s[r][c] = 0.0f;

#pragma unroll
        for (int d = 0; d < 32; ++d) {
            float4 qa = *reinterpret_cast<const float4*>(&Qs[d][4 * ty]);
            float4 ka = *reinterpret_cast<const float4*>(&Ks[d][4 * tx]);
            float qv[4] = {qa.x, qa.y, qa.z, qa.w};
            float kv[4] = {ka.x, ka.y, ka.z, ka.w};
#pragma unroll
            for (int r = 0; r < 4; ++r)
#pragma unroll
                for (int c = 0; c < 4; ++c)
                    s[r][c] = fmaf(qv[r], kv[c], s[r][c]);
        }

        float eKc[4], wKc[4];
#pragma unroll
        for (int c = 0; c < 4; ++c) { eKc[c] = eK[4 * tx + c]; wKc[c] = wK[4 * tx + c]; }
#pragma unroll
        for (int r = 0; r < 4; ++r)
#pragma unroll
            for (int c = 0; c < 4; ++c) {
                float ed = (eKc[c] - eQr[r]) * 1e-3f;
                ed = fmaxf(ed, 0.0f);
                float z = (wQr[r] + wKc[c]) * 0.5f - 5.0f;
                float wf = 1.0f / (1.0f + __expf(-z));
                float bia = -alpha * ed * (1.0f - beta * wf);
                bia = fminf(fmaxf(bia, -10.0f), 0.0f);
                s[r][c] = fmaf(s[r][c], scale, bia);
            }

#pragma unroll
        for (int r = 0; r < 4; ++r) {
            float mt = fmaxf(fmaxf(s[r][0], s[r][1]), fmaxf(s[r][2], s[r][3]));
#pragma unroll
            for (int o = 1; o < 16; o <<= 1)
                mt = fmaxf(mt, __shfl_xor_sync(0xffffffffu, mt, o));
            float mn = fmaxf(m[r], mt);
            float sc = __expf(m[r] - mn);
            float rs = 0.0f;
#pragma unroll
            for (int c = 0; c < 4; ++c) {
                float p = __expf(s[r][c] - mn);
                s[r][c] = p;
                rs += p;
            }
#pragma unroll
            for (int o = 1; o < 16; o <<= 1)
                rs += __shfl_xor_sync(0xffffffffu, rs, o);
            l[r] = l[r] * sc + rs;
            m[r] = mn;
            acc[r][0] *= sc;
            acc[r][1] *= sc;
        }

#pragma unroll
        for (int r = 0; r < 4; ++r)
#pragma unroll
            for (int c = 0; c < 4; ++c)
                Ps[4 * tx + c][4 * ty + r] = s[r][c];
        __syncthreads();

#pragma unroll 16
        for (int j = 0; j < 64; ++j) {
            float4 pa = *reinterpret_cast<const float4*>(&Ps[j][4 * ty]);
            float2 va = *reinterpret_cast<const float2*>(&Vs[j][2 * tx]);
            acc[0][0] = fmaf(pa.x, va.x, acc[0][0]);
            acc[0][1] = fmaf(pa.x, va.y, acc[0][1]);
            acc[1][0] = fmaf(pa.y, va.x, acc[1][0]);
            acc[1][1] = fmaf(pa.y, va.y, acc[1][1]);
            acc[2][0] = fmaf(pa.z, va.x, acc[2][0]);
            acc[2][1] = fmaf(pa.z, va.y, acc[2][1]);
            acc[3][0] = fmaf(pa.w, va.x, acc[3][0]);
            acc[3][1] = fmaf(pa.w, va.y, acc[3][1]);
        }
    }

#pragma unroll
    for (int r = 0; r < 4; ++r) {
        float inv = 1.0f / l[r];
        int orow = qrow0 + 4 * ty + r;
        float* op = outp + (size_t)orow * C_ + h * HD_ + 2 * tx;
        op[0] = acc[r][0] * inv;
        op[1] = acc[r][1] * inv;
    }
}

// ---------------------------------------------------------------------------
// launch
// ---------------------------------------------------------------------------
extern "C" void kernel_launch(void* const* d_in, const int* in_sizes, int n_in,
                              void* d_out, int out_size) {
    const float* x     = (const float*)d_in[0];
    const float* elev  = (const float*)d_in[1];
    const float* uw    = (const float*)d_in[2];
    const float* vw    = (const float*)d_in[3];
    const float* wqkv  = (const float*)d_in[4];
    const float* wproj = (const float*)d_in[5];
    const float* bproj = (const float*)d_in[6];
    const float* alpha = (const float*)d_in[7];
    const float* beta  = (const float*)d_in[8];
    float* out = (float*)d_out;

    float *qkv_p, *attn_p, *ws_p;
    cudaGetSymbolAddress((void**)&qkv_p, g_qkv);
    cudaGetSymbolAddress((void**)&attn_p, g_attn);
    cudaGetSymbolAddress((void**)&ws_p, g_ws);

    // 1) wind strength
    wind_kernel<<<32, 256>>>(uw, vw, ws_p);

    // 2) qkv = x @ w_qkv^T : bf16-split tensor cores
    gemm_mma<false><<<dim3(768 / 128, 8192 / 128), 256>>>(
        x, wqkv, nullptr, qkv_p, 768);

    // 3) fused biased attention
    attn_kernel<<<dim3(16, NH_, B_), 256>>>(qkv_p, elev, ws_p, alpha, beta, attn_p);

    // 4) out = attn @ w_proj^T + b_proj : bf16-split tensor cores
    gemm_mma<true><<<dim3(256 / 128, 8192 / 128), 256>>>(
        attn_p, wproj, bproj, out, 256);
}

// round 5
// speedup vs baseline: 2.9458x; 1.8547x over previous
#include <cuda_runtime.h>
#include <cuda_bf16.h>
#include <math.h>
#include <cstdint>

// ---------------------------------------------------------------------------
// PhysicsGuidedAttentionCorrected
// B=8, N=1024, C=256, NUM_HEADS=8, hd=32
// R5: bias precomputed once per (b,i,j); attention on mma.sync bf16 hi/lo
//     split tensor cores (flash-style, P kept in registers); GEMMs as R4.
// ---------------------------------------------------------------------------

#define B_ 8
#define N_ 1024
#define C_ 256
#define NH_ 8
#define HD_ 32

// scratch (device globals; no allocations allowed)
__device__ float g_qkv[B_ * N_ * 3 * C_];
__device__ float g_attn[B_ * N_ * C_];
__device__ float g_ws[B_ * N_];
__device__ float g_bias[B_ * N_ * N_];     // 33.5 MB

// ---------------------------------------------------------------------------
// helpers
// ---------------------------------------------------------------------------
__device__ __forceinline__ uint32_t smem_u32(const void* p) {
    uint32_t a;
    asm("{ .reg .u64 t; cvta.to.shared.u64 t, %1; cvt.u32.u64 %0, t; }"
        : "=r"(a) : "l"(p));
    return a;
}

#define LDSM_X4(r0, r1, r2, r3, addr)                                        \
    asm volatile("ldmatrix.sync.aligned.m8n8.x4.shared.b16 {%0,%1,%2,%3}, [%4];" \
                 : "=r"(r0), "=r"(r1), "=r"(r2), "=r"(r3) : "r"(addr))

#define MMA_BF16(d, a0, a1, a2, a3, b0, b1)                                  \
    asm volatile("mma.sync.aligned.m16n8k16.row.col.f32.bf16.bf16.f32 "      \
                 "{%0,%1,%2,%3}, {%4,%5,%6,%7}, {%8,%9}, {%0,%1,%2,%3};"     \
                 : "+f"((d)[0]), "+f"((d)[1]), "+f"((d)[2]), "+f"((d)[3])    \
                 : "r"(a0), "r"(a1), "r"(a2), "r"(a3), "r"(b0), "r"(b1))

__device__ __forceinline__ void split2(float x, float y,
                                       __nv_bfloat162& hi, __nv_bfloat162& lo) {
    __nv_bfloat16 hx = __float2bfloat16_rn(x);
    __nv_bfloat16 hy = __float2bfloat16_rn(y);
    hi = __nv_bfloat162(hx, hy);
    lo = __nv_bfloat162(__float2bfloat16_rn(x - __bfloat162float(hx)),
                        __float2bfloat16_rn(y - __bfloat162float(hy)));
}
__device__ __forceinline__ uint32_t u32of(__nv_bfloat162 v) {
    return *reinterpret_cast<uint32_t*>(&v);
}

// ---------------------------------------------------------------------------
// wind strength
// ---------------------------------------------------------------------------
__global__ void wind_kernel(const float* __restrict__ u,
                            const float* __restrict__ v,
                            float* __restrict__ ws) {
    int t = blockIdx.x * blockDim.x + threadIdx.x;
    if (t >= B_ * N_) return;
    int b = t >> 10;
    int n = t & 1023;
    int r = n >> 5;
    int c = n & 31;
    const float* ub = u + b * 4096;
    const float* vb = v + b * 4096;
    float s = 0.0f;
#pragma unroll
    for (int dr = 0; dr < 2; ++dr)
#pragma unroll
        for (int dc = 0; dc < 2; ++dc) {
            int idx = (2 * r + dr) * 64 + (2 * c + dc);
            float uu = ub[idx], vv = vb[idx];
            s += sqrtf(uu * uu + vv * vv + 1e-8f);
        }
    ws[t] = s * 0.25f;
}

// ---------------------------------------------------------------------------
// bias precompute: bias[b,i,j] (head-independent)
// one block per (b,i); 256 threads x 4 j each
// ---------------------------------------------------------------------------
__global__ __launch_bounds__(256)
void bias_kernel(const float* __restrict__ elev, const float* __restrict__ ws,
                 const float* __restrict__ alpha_p, const float* __restrict__ beta_p,
                 float* __restrict__ bias) {
    const int bi = blockIdx.x;          // b*1024 + i
    const int b = bi >> 10;
    const float alpha = *alpha_p;
    const float beta = *beta_p;
    const float e_i = elev[bi];
    const float w_i = ws[bi];
    const float* ej = elev + b * 1024;
    const float* wj = ws + b * 1024;
    float* bp = bias + (size_t)bi * 1024;
    const int j4 = threadIdx.x * 4;
    float4 e = *reinterpret_cast<const float4*>(ej + j4);
    float4 w = *reinterpret_cast<const float4*>(wj + j4);
    float4 o;
#pragma unroll
    for (int k = 0; k < 4; ++k) {
        float evk = (&e.x)[k], wvk = (&w.x)[k];
        float ed = fmaxf((evk - e_i) * 1e-3f, 0.0f);
        float z = (w_i + wvk) * 0.5f - 5.0f;
        float wf = 1.0f / (1.0f + __expf(-z));
        float bia = -alpha * ed * (1.0f - beta * wf);
        (&o.x)[k] = fminf(fmaxf(bia, -10.0f), 0.0f);
    }
    *reinterpret_cast<float4*>(bp + j4) = o;
}

// ---------------------------------------------------------------------------
// bf16-split tensor-core GEMM (R4, proven): C = A*B^T (+bias)
// ---------------------------------------------------------------------------
#define PITCH 40

template <bool HAS_BIAS>
__global__ __launch_bounds__(256)
void gemm_mma(const float* __restrict__ A, const float* __restrict__ B,
              const float* __restrict__ bias, float* __restrict__ C, int N) {
    __shared__ __align__(16) __nv_bfloat16 Ah[128 * PITCH];
    __shared__ __align__(16) __nv_bfloat16 Al[128 * PITCH];
    __shared__ __align__(16) __nv_bfloat16 Bh[128 * PITCH];
    __shared__ __align__(16) __nv_bfloat16 Bl[128 * PITCH];

    const int tid = threadIdx.x;
    const int lane = tid & 31;
    const int wid = tid >> 5;
    const int wm = wid & 1;
    const int wn = wid >> 1;
    const int bx = blockIdx.x;
    const int by = blockIdx.y;

    const float* Ag = A + (size_t)by * 128 * 256;
    const float* Bg = B + (size_t)bx * 128 * 256;

    float acc[4][4][4];
#pragma unroll
    for (int mt = 0; mt < 4; ++mt)
#pragma unroll
        for (int nt = 0; nt < 4; ++nt)
#pragma unroll
            for (int i = 0; i < 4; ++i) acc[mt][nt][i] = 0.0f;

    const int a_row = (lane & 15);
    const int a_ch  = (lane & 16) ? 8 : 0;
    const int b_row = (lane & 7) + ((lane & 16) ? 8 : 0);
    const int b_ch  = (lane & 8) ? 8 : 0;

    const uint32_t sAh = smem_u32(Ah), sAl = smem_u32(Al);
    const uint32_t sBh = smem_u32(Bh), sBl = smem_u32(Bl);

    const uint32_t aoff = (uint32_t)((wm * 64 + a_row) * PITCH + a_ch) * 2;
    const uint32_t boff = (uint32_t)((wn * 32 + b_row) * PITCH + b_ch) * 2;

#pragma unroll 1
    for (int kb = 0; kb < 8; ++kb) {
        __syncthreads();
#pragma unroll
        for (int i = 0; i < 4; ++i) {
            int slot = tid + i * 256;
            int row = slot >> 3;
            int c4 = (slot & 7) * 4;
            float4 av = *reinterpret_cast<const float4*>(
                Ag + (size_t)row * 256 + kb * 32 + c4);
            __nv_bfloat162 h01, l01, h23, l23;
            split2(av.x, av.y, h01, l01);
            split2(av.z, av.w, h23, l23);
            *reinterpret_cast<__nv_bfloat162*>(&Ah[row * PITCH + c4])     = h01;
            *reinterpret_cast<__nv_bfloat162*>(&Ah[row * PITCH + c4 + 2]) = h23;
            *reinterpret_cast<__nv_bfloat162*>(&Al[row * PITCH + c4])     = l01;
            *reinterpret_cast<__nv_bfloat162*>(&Al[row * PITCH + c4 + 2]) = l23;
            float4 bv = *reinterpret_cast<const float4*>(
                Bg + (size_t)row * 256 + kb * 32 + c4);
            split2(bv.x, bv.y, h01, l01);
            split2(bv.z, bv.w, h23, l23);
            *reinterpret_cast<__nv_bfloat162*>(&Bh[row * PITCH + c4])     = h01;
            *reinterpret_cast<__nv_bfloat162*>(&Bh[row * PITCH + c4 + 2]) = h23;
            *reinterpret_cast<__nv_bfloat162*>(&Bl[row * PITCH + c4])     = l01;
            *reinterpret_cast<__nv_bfloat162*>(&Bl[row * PITCH + c4 + 2]) = l23;
        }
        __syncthreads();

#pragma unroll
        for (int kk = 0; kk < 2; ++kk) {
            const uint32_t kof = (uint32_t)(kk * 16) * 2;
            uint32_t bhf[2][4], blf[2][4];
#pragma unroll
            for (int ntp = 0; ntp < 2; ++ntp) {
                uint32_t ba = boff + (uint32_t)(ntp * 16 * PITCH) * 2 + kof;
                LDSM_X4(bhf[ntp][0], bhf[ntp][1], bhf[ntp][2], bhf[ntp][3], sBh + ba);
                LDSM_X4(blf[ntp][0], blf[ntp][1], blf[ntp][2], blf[ntp][3], sBl + ba);
            }
#pragma unroll
            for (int mt = 0; mt < 4; ++mt) {
                uint32_t aa = aoff + (uint32_t)(mt * 16 * PITCH) * 2 + kof;
                uint32_t ah0, ah1, ah2, ah3, al0, al1, al2, al3;
                LDSM_X4(ah0, ah1, ah2, ah3, sAh + aa);
                LDSM_X4(al0, al1, al2, al3, sAl + aa);
#pragma unroll
                for (int nt = 0; nt < 4; ++nt) {
                    const int ntp = nt >> 1;
                    const int hb = (nt & 1) * 2;
                    MMA_BF16(acc[mt][nt], ah0, ah1, ah2, ah3,
                             bhf[ntp][hb], bhf[ntp][hb + 1]);
                    MMA_BF16(acc[mt][nt], ah0, ah1, ah2, ah3,
                             blf[ntp][hb], blf[ntp][hb + 1]);
                    MMA_BF16(acc[mt][nt], al0, al1, al2, al3,
                             bhf[ntp][hb], bhf[ntp][hb + 1]);
                }
            }
        }
    }

    const int gid = lane >> 2;
    const int tig = lane & 3;
#pragma unroll
    for (int mt = 0; mt < 4; ++mt) {
        int row = by * 128 + wm * 64 + mt * 16 + gid;
#pragma unroll
        for (int nt = 0; nt < 4; ++nt) {
            int col = bx * 128 + wn * 32 + nt * 8 + 2 * tig;
            float2 v0 = make_float2(acc[mt][nt][0], acc[mt][nt][1]);
            float2 v1 = make_float2(acc[mt][nt][2], acc[mt][nt][3]);
            if (HAS_BIAS) {
                float2 bb = *reinterpret_cast<const float2*>(bias + col);
                v0.x += bb.x; v0.y += bb.y;
                v1.x += bb.x; v1.y += bb.y;
            }
            *reinterpret_cast<float2*>(C + (size_t)row * N + col) = v0;
            *reinterpret_cast<float2*>(C + (size_t)(row + 8) * N + col) = v1;
        }
    }
}

// ---------------------------------------------------------------------------
// tensor-core flash attention.
// block = 128 queries x (b,h). 8 warps; warp w owns rows w*16..w*16+15.
// S = QK^T via 3-term bf16 split; P kept in registers -> A-fragments for PV.
// ---------------------------------------------------------------------------
#define VP 72    // Vt pitch (keys dim), conflict-free for ldmatrix

__global__ __launch_bounds__(256)
void attn_mma(const float* __restrict__ qkv, const float* __restrict__ bias,
              float* __restrict__ outp) {
    __shared__ __align__(16) __nv_bfloat16 Qh[128 * PITCH];
    __shared__ __align__(16) __nv_bfloat16 Ql[128 * PITCH];
    __shared__ __align__(16) __nv_bfloat16 Kh[64 * PITCH];
    __shared__ __align__(16) __nv_bfloat16 Kl[64 * PITCH];
    __shared__ __align__(16) __nv_bfloat16 Vth[32 * VP];
    __shared__ __align__(16) __nv_bfloat16 Vtl[32 * VP];

    const int tid = threadIdx.x;
    const int lane = tid & 31;
    const int w = tid >> 5;
    const int gid = lane >> 2;
    const int tig = lane & 3;
    const int qc = blockIdx.x;      // 0..7
    const int h  = blockIdx.y;      // 0..7
    const int b  = blockIdx.z;      // 0..7

    const float scale = 0.17677669529663687f;   // 1/sqrt(32)
    const int qrow0 = b * N_ + qc * 128;

    // load Q tile (128x32) -> hi/lo bf16
#pragma unroll
    for (int i = 0; i < 4; ++i) {
        int slot = tid + i * 256;       // 0..1023
        int row = slot >> 3;
        int c4 = (slot & 7) * 4;
        float4 q = *reinterpret_cast<const float4*>(
            qkv + (size_t)(qrow0 + row) * 768 + h * HD_ + c4);
        __nv_bfloat162 h01, l01, h23, l23;
        split2(q.x, q.y, h01, l01);
        split2(q.z, q.w, h23, l23);
        *reinterpret_cast<__nv_bfloat162*>(&Qh[row * PITCH + c4])     = h01;
        *reinterpret_cast<__nv_bfloat162*>(&Qh[row * PITCH + c4 + 2]) = h23;
        *reinterpret_cast<__nv_bfloat162*>(&Ql[row * PITCH + c4])     = l01;
        *reinterpret_cast<__nv_bfloat162*>(&Ql[row * PITCH + c4 + 2]) = l23;
    }

    const uint32_t sQh = smem_u32(Qh), sQl = smem_u32(Ql);
    const uint32_t sKh = smem_u32(Kh), sKl = smem_u32(Kl);
    const uint32_t sVh = smem_u32(Vth), sVl = smem_u32(Vtl);

    const uint32_t aoff =
        (uint32_t)((w * 16 + (lane & 15)) * PITCH + ((lane & 16) ? 8 : 0)) * 2;
    const uint32_t koff =
        (uint32_t)(((lane & 7) + ((lane & 16) ? 8 : 0)) * PITCH +
                   ((lane & 8) ? 8 : 0)) * 2;
    const uint32_t voff =
        (uint32_t)(((lane & 7) + ((lane & 16) ? 8 : 0)) * VP +
                   ((lane & 8) ? 8 : 0)) * 2;

    float m0 = -1e30f, m1 = -1e30f, l0 = 0.0f, l1 = 0.0f;
    float oacc[4][4];
#pragma unroll
    for (int nt = 0; nt < 4; ++nt)
#pragma unroll
        for (int i = 0; i < 4; ++i) oacc[nt][i] = 0.0f;

    const int qi0 = qc * 128 + w * 16 + gid;         // local i within batch
    const float* bias_b = bias + ((size_t)b << 20);   // b*1024*1024

#pragma unroll 1
    for (int kt = 0; kt < 16; ++kt) {
        __syncthreads();
        const int krow0 = b * N_ + kt * 64;
        // load K (64x32) hi/lo and V transposed (hd x keys) hi/lo
#pragma unroll
        for (int i = 0; i < 2; ++i) {
            int slot = tid + i * 256;   // 0..511
            int row = slot >> 3;
            int c4 = (slot & 7) * 4;
            size_t base = (size_t)(krow0 + row) * 768 + 256 + h * HD_ + c4;
            float4 kv = *reinterpret_cast<const float4*>(qkv + base);
            __nv_bfloat162 h01, l01, h23, l23;
            split2(kv.x, kv.y, h01, l01);
            split2(kv.z, kv.w, h23, l23);
            *reinterpret_cast<__nv_bfloat162*>(&Kh[row * PITCH + c4])     = h01;
            *reinterpret_cast<__nv_bfloat162*>(&Kh[row * PITCH + c4 + 2]) = h23;
            *reinterpret_cast<__nv_bfloat162*>(&Kl[row * PITCH + c4])     = l01;
            *reinterpret_cast<__nv_bfloat162*>(&Kl[row * PITCH + c4 + 2]) = l23;
            float4 vv = *reinterpret_cast<const float4*>(qkv + base + 256);
#pragma unroll
            for (int j = 0; j < 4; ++j) {
                float vj = (&vv.x)[j];
                __nv_bfloat16 hv = __float2bfloat16_rn(vj);
                __nv_bfloat16 lv = __float2bfloat16_rn(vj - __bfloat162float(hv));
                Vth[(c4 + j) * VP + row] = hv;
                Vtl[(c4 + j) * VP + row] = lv;
            }
        }
        __syncthreads();

        // ---- S = Q K^T (3-term split), 8 n-tiles of 8 keys ----
        float sacc[8][4];
#pragma unroll
        for (int nt = 0; nt < 8; ++nt)
#pragma unroll
            for (int i = 0; i < 4; ++i) sacc[nt][i] = 0.0f;

#pragma unroll
        for (int kk = 0; kk < 2; ++kk) {
            const uint32_t kof = (uint32_t)(kk * 16) * 2;
            uint32_t ah0, ah1, ah2, ah3, al0, al1, al2, al3;
            LDSM_X4(ah0, ah1, ah2, ah3, sQh + aoff + kof);
            LDSM_X4(al0, al1, al2, al3, sQl + aoff + kof);
            uint32_t bh[4][4], bl[4][4];
#pragma unroll
            for (int ntp = 0; ntp < 4; ++ntp) {
                uint32_t ba = koff + (uint32_t)(ntp * 16 * PITCH) * 2 + kof;
                LDSM_X4(bh[ntp][0], bh[ntp][1], bh[ntp][2], bh[ntp][3], sKh + ba);
                LDSM_X4(bl[ntp][0], bl[ntp][1], bl[ntp][2], bl[ntp][3], sKl + ba);
            }
#pragma unroll
            for (int nt = 0; nt < 8; ++nt) {
                const int ntp = nt >> 1;
                const int hb = (nt & 1) * 2;
                MMA_BF16(sacc[nt], ah0, ah1, ah2, ah3, bh[ntp][hb], bh[ntp][hb + 1]);
                MMA_BF16(sacc[nt], ah0, ah1, ah2, ah3, bl[ntp][hb], bl[ntp][hb + 1]);
                MMA_BF16(sacc[nt], al0, al1, al2, al3, bh[ntp][hb], bh[ntp][hb + 1]);
            }
        }

        // ---- scale + bias (precomputed, head-independent) ----
#pragma unroll
        for (int nt = 0; nt < 8; ++nt) {
            int jc = kt * 64 + nt * 8 + 2 * tig;
            float2 bb0 = *reinterpret_cast<const float2*>(
                bias_b + (size_t)qi0 * 1024 + jc);
            float2 bb1 = *reinterpret_cast<const float2*>(
                bias_b + (size_t)(qi0 + 8) * 1024 + jc);
            sacc[nt][0] = fmaf(sacc[nt][0], scale, bb0.x);
            sacc[nt][1] = fmaf(sacc[nt][1], scale, bb0.y);
            sacc[nt][2] = fmaf(sacc[nt][2], scale, bb1.x);
            sacc[nt][3] = fmaf(sacc[nt][3], scale, bb1.y);
        }

        // ---- online softmax (rows gid and gid+8) ----
        float mt0 = -1e30f, mt1 = -1e30f;
#pragma unroll
        for (int nt = 0; nt < 8; ++nt) {
            mt0 = fmaxf(mt0, fmaxf(sacc[nt][0], sacc[nt][1]));
            mt1 = fmaxf(mt1, fmaxf(sacc[nt][2], sacc[nt][3]));
        }
        mt0 = fmaxf(mt0, __shfl_xor_sync(0xffffffffu, mt0, 1));
        mt0 = fmaxf(mt0, __shfl_xor_sync(0xffffffffu, mt0, 2));
        mt1 = fmaxf(mt1, __shfl_xor_sync(0xffffffffu, mt1, 1));
        mt1 = fmaxf(mt1, __shfl_xor_sync(0xffffffffu, mt1, 2));
        float mn0 = fmaxf(m0, mt0), mn1 = fmaxf(m1, mt1);
        float sc0 = __expf(m0 - mn0), sc1 = __expf(m1 - mn1);
        float rs0 = 0.0f, rs1 = 0.0f;
#pragma unroll
        for (int nt = 0; nt < 8; ++nt) {
            sacc[nt][0] = __expf(sacc[nt][0] - mn0);
            sacc[nt][1] = __expf(sacc[nt][1] - mn0);
            sacc[nt][2] = __expf(sacc[nt][2] - mn1);
            sacc[nt][3] = __expf(sacc[nt][3] - mn1);
            rs0 += sacc[nt][0] + sacc[nt][1];
            rs1 += sacc[nt][2] + sacc[nt][3];
        }
        rs0 += __shfl_xor_sync(0xffffffffu, rs0, 1);
        rs0 += __shfl_xor_sync(0xffffffffu, rs0, 2);
        rs1 += __shfl_xor_sync(0xffffffffu, rs1, 1);
        rs1 += __shfl_xor_sync(0xffffffffu, rs1, 2);
        l0 = l0 * sc0 + rs0;
        l1 = l1 * sc1 + rs1;
        m0 = mn0; m1 = mn1;
#pragma unroll
        for (int nt = 0; nt < 4; ++nt) {
            oacc[nt][0] *= sc0; oacc[nt][1] *= sc0;
            oacc[nt][2] *= sc1; oacc[nt][3] *= sc1;
        }

        // ---- O += P V : P fragments direct from sacc (registers) ----
#pragma unroll
        for (int ks = 0; ks < 4; ++ks) {
            __nv_bfloat162 hh, ll;
            uint32_t pah[4], pal[4];
            split2(sacc[2 * ks][0],     sacc[2 * ks][1],     hh, ll);
            pah[0] = u32of(hh); pal[0] = u32of(ll);
            split2(sacc[2 * ks][2],     sacc[2 * ks][3],     hh, ll);
            pah[1] = u32of(hh); pal[1] = u32of(ll);
            split2(sacc[2 * ks + 1][0], sacc[2 * ks + 1][1], hh, ll);
            pah[2] = u32of(hh); pal[2] = u32of(ll);
            split2(sacc[2 * ks + 1][2], sacc[2 * ks + 1][3], hh, ll);
            pah[3] = u32of(hh); pal[3] = u32of(ll);

            const uint32_t kof = (uint32_t)(ks * 16) * 2;
            uint32_t vh[2][4], vl[2][4];
#pragma unroll
            for (int ntp = 0; ntp < 2; ++ntp) {
                uint32_t va = voff + (uint32_t)(ntp * 16 * VP) * 2 + kof;
                LDSM_X4(vh[ntp][0], vh[ntp][1], vh[ntp][2], vh[ntp][3], sVh + va);
                LDSM_X4(vl[ntp][0], vl[ntp][1], vl[ntp][2], vl[ntp][3], sVl + va);
            }
#pragma unroll
            for (int nt = 0; nt < 4; ++nt) {
                const int ntp = nt >> 1;
                const int hb = (nt & 1) * 2;
                MMA_BF16(oacc[nt], pah[0], pah[1], pah[2], pah[3],
                         vh[ntp][hb], vh[ntp][hb + 1]);
                MMA_BF16(oacc[nt], pah[0], pah[1], pah[2], pah[3],
                         vl[ntp][hb], vl[ntp][hb + 1]);
                MMA_BF16(oacc[nt], pal[0], pal[1], pal[2], pal[3],
                         vh[ntp][hb], vh[ntp][hb + 1]);
            }
        }
    }

    // ---- epilogue ----
    const float inv0 = 1.0f / l0;
    const float inv1 = 1.0f / l1;
    const int row0 = qrow0 + w * 16 + gid;
#pragma unroll
    for (int nt = 0; nt < 4; ++nt) {
        int col = h * HD_ + nt * 8 + 2 * tig;
        float2 v0 = make_float2(oacc[nt][0] * inv0, oacc[nt][1] * inv0);
        float2 v1 = make_float2(oacc[nt][2] * inv1, oacc[nt][3] * inv1);
        *reinterpret_cast<float2*>(outp + (size_t)row0 * C_ + col) = v0;
        *reinterpret_cast<float2*>(outp + (size_t)(row0 + 8) * C_ + col) = v1;
    }
}

// ---------------------------------------------------------------------------
// launch
// ---------------------------------------------------------------------------
extern "C" void kernel_launch(void* const* d_in, const int* in_sizes, int n_in,
                              void* d_out, int out_size) {
    const float* x     = (const float*)d_in[0];
    const float* elev  = (const float*)d_in[1];
    const float* uw    = (const float*)d_in[2];
    const float* vw    = (const float*)d_in[3];
    const float* wqkv  = (const float*)d_in[4];
    const float* wproj = (const float*)d_in[5];
    const float* bproj = (const float*)d_in[6];
    const float* alpha = (const float*)d_in[7];
    const float* beta  = (const float*)d_in[8];
    float* out = (float*)d_out;

    float *qkv_p, *attn_p, *ws_p, *bias_p;
    cudaGetSymbolAddress((void**)&qkv_p, g_qkv);
    cudaGetSymbolAddress((void**)&attn_p, g_attn);
    cudaGetSymbolAddress((void**)&ws_p, g_ws);
    cudaGetSymbolAddress((void**)&bias_p, g_bias);

    // 1) wind strength
    wind_kernel<<<32, 256>>>(uw, vw, ws_p);

    // 2) bias precompute [B,N,N]
    bias_kernel<<<B_ * N_, 256>>>(elev, ws_p, alpha, beta, bias_p);

    // 3) qkv = x @ w_qkv^T
    gemm_mma<false><<<dim3(768 / 128, 8192 / 128), 256>>>(
        x, wqkv, nullptr, qkv_p, 768);

    // 4) tensor-core flash attention with precomputed bias
    attn_mma<<<dim3(8, NH_, B_), 256>>>(qkv_p, bias_p, attn_p);

    // 5) out = attn @ w_proj^T + b_proj
    gemm_mma<true><<<dim3(256 / 128, 8192 / 128), 256>>>(
        attn_p, wproj, bproj, out, 256);
}

// round 6
// speedup vs baseline: 3.0079x; 1.0211x over previous
#include <cuda_runtime.h>
#include <cuda_bf16.h>
#include <math.h>
#include <cstdint>

// ---------------------------------------------------------------------------
// PhysicsGuidedAttentionCorrected
// B=8, N=1024, C=256, NUM_HEADS=8, hd=32
// R6: all fp32->bf16 hi/lo splits hoisted out of hot loops; GEMM/attention
//     operate on pre-split bf16; V via ldmatrix.trans (no scalar transpose);
//     Q fragments hoisted out of the key loop.
// ---------------------------------------------------------------------------

#define B_ 8
#define N_ 1024
#define C_ 256
#define NH_ 8
#define HD_ 32

// scratch (device globals; no allocations allowed)
__device__ float g_ws[B_ * N_];
__device__ float g_bias[B_ * N_ * N_];                 // 33.5 MB
__device__ __nv_bfloat16 g_xh[B_ * N_ * C_];
__device__ __nv_bfloat16 g_xl[B_ * N_ * C_];
__device__ __nv_bfloat16 g_wqkvh[3 * C_ * C_];
__device__ __nv_bfloat16 g_wqkvl[3 * C_ * C_];
__device__ __nv_bfloat16 g_wprojh[C_ * C_];
__device__ __nv_bfloat16 g_wprojl[C_ * C_];
__device__ __nv_bfloat16 g_qkvh[B_ * N_ * 3 * C_];
__device__ __nv_bfloat16 g_qkvl[B_ * N_ * 3 * C_];
__device__ __nv_bfloat16 g_attnh[B_ * N_ * C_];
__device__ __nv_bfloat16 g_attnl[B_ * N_ * C_];

// ---------------------------------------------------------------------------
// helpers
// ---------------------------------------------------------------------------
__device__ __forceinline__ uint32_t smem_u32(const void* p) {
    uint32_t a;
    asm("{ .reg .u64 t; cvta.to.shared.u64 t, %1; cvt.u32.u64 %0, t; }"
        : "=r"(a) : "l"(p));
    return a;
}

#define LDSM_X4(r0, r1, r2, r3, addr)                                        \
    asm volatile("ldmatrix.sync.aligned.m8n8.x4.shared.b16 {%0,%1,%2,%3}, [%4];" \
                 : "=r"(r0), "=r"(r1), "=r"(r2), "=r"(r3) : "r"(addr))

#define LDSM_X4T(r0, r1, r2, r3, addr)                                       \
    asm volatile("ldmatrix.sync.aligned.m8n8.x4.trans.shared.b16 {%0,%1,%2,%3}, [%4];" \
                 : "=r"(r0), "=r"(r1), "=r"(r2), "=r"(r3) : "r"(addr))

#define MMA_BF16(d, a0, a1, a2, a3, b0, b1)                                  \
    asm volatile("mma.sync.aligned.m16n8k16.row.col.f32.bf16.bf16.f32 "      \
                 "{%0,%1,%2,%3}, {%4,%5,%6,%7}, {%8,%9}, {%0,%1,%2,%3};"     \
                 : "+f"((d)[0]), "+f"((d)[1]), "+f"((d)[2]), "+f"((d)[3])    \
                 : "r"(a0), "r"(a1), "r"(a2), "r"(a3), "r"(b0), "r"(b1))

__device__ __forceinline__ void split2(float x, float y,
                                       __nv_bfloat162& hi, __nv_bfloat162& lo) {
    __nv_bfloat16 hx = __float2bfloat16_rn(x);
    __nv_bfloat16 hy = __float2bfloat16_rn(y);
    hi = __nv_bfloat162(hx, hy);
    lo = __nv_bfloat162(__float2bfloat16_rn(x - __bfloat162float(hx)),
                        __float2bfloat16_rn(y - __bfloat162float(hy)));
}
__device__ __forceinline__ uint32_t u32of(__nv_bfloat162 v) {
    return *reinterpret_cast<uint32_t*>(&v);
}

// ---------------------------------------------------------------------------
// wind strength
// ---------------------------------------------------------------------------
__global__ void wind_kernel(const float* __restrict__ u,
                            const float* __restrict__ v,
                            float* __restrict__ ws) {
    int t = blockIdx.x * blockDim.x + threadIdx.x;
    if (t >= B_ * N_) return;
    int b = t >> 10;
    int n = t & 1023;
    int r = n >> 5;
    int c = n & 31;
    const float* ub = u + b * 4096;
    const float* vb = v + b * 4096;
    float s = 0.0f;
#pragma unroll
    for (int dr = 0; dr < 2; ++dr)
#pragma unroll
        for (int dc = 0; dc < 2; ++dc) {
            int idx = (2 * r + dr) * 64 + (2 * c + dc);
            float uu = ub[idx], vv = vb[idx];
            s += sqrtf(uu * uu + vv * vv + 1e-8f);
        }
    ws[t] = s * 0.25f;
}

// ---------------------------------------------------------------------------
// bias precompute: bias[b,i,j] (head-independent)
// ---------------------------------------------------------------------------
__global__ __launch_bounds__(256)
void bias_kernel(const float* __restrict__ elev, const float* __restrict__ ws,
                 const float* __restrict__ alpha_p, const float* __restrict__ beta_p,
                 float* __restrict__ bias) {
    const int bi = blockIdx.x;
    const int b = bi >> 10;
    const float alpha = *alpha_p;
    const float beta = *beta_p;
    const float e_i = elev[bi];
    const float w_i = ws[bi];
    const float* ej = elev + b * 1024;
    const float* wj = ws + b * 1024;
    float* bp = bias + (size_t)bi * 1024;
    const int j4 = threadIdx.x * 4;
    float4 e = *reinterpret_cast<const float4*>(ej + j4);
    float4 w = *reinterpret_cast<const float4*>(wj + j4);
    float4 o;
#pragma unroll
    for (int k = 0; k < 4; ++k) {
        float evk = (&e.x)[k], wvk = (&w.x)[k];
        float ed = fmaxf((evk - e_i) * 1e-3f, 0.0f);
        float z = (w_i + wvk) * 0.5f - 5.0f;
        float wf = 1.0f / (1.0f + __expf(-z));
        float bia = -alpha * ed * (1.0f - beta * wf);
        (&o.x)[k] = fminf(fmaxf(bia, -10.0f), 0.0f);
    }
    *reinterpret_cast<float4*>(bp + j4) = o;
}

// ---------------------------------------------------------------------------
// fp32 -> bf16 hi/lo split converter (vectorized, 4 floats/thread)
// ---------------------------------------------------------------------------
__global__ void convert_split(const float* __restrict__ in,
                              __nv_bfloat16* __restrict__ hi,
                              __nv_bfloat16* __restrict__ lo, int n4) {
    int i = blockIdx.x * blockDim.x + threadIdx.x;
    if (i >= n4) return;
    float4 v = reinterpret_cast<const float4*>(in)[i];
    __nv_bfloat162 h01, l01, h23, l23;
    split2(v.x, v.y, h01, l01);
    split2(v.z, v.w, h23, l23);
    uint2 hv = make_uint2(u32of(h01), u32of(h23));
    uint2 lv = make_uint2(u32of(l01), u32of(l23));
    *reinterpret_cast<uint2*>(hi + 4 * i) = hv;
    *reinterpret_cast<uint2*>(lo + 4 * i) = lv;
}

// ---------------------------------------------------------------------------
// bf16-split tensor-core GEMM from PRE-SPLIT operands.
// C[m,n] = sum_k A[m,k]*B[n,k]; K=256; CTA 128x128; 8 warps (2M x 4N).
// SPLIT_OUT: write hi/lo bf16; else f32 (+bias).
// ---------------------------------------------------------------------------
#define PITCH 40

template <bool HAS_BIAS, bool SPLIT_OUT>
__global__ __launch_bounds__(256)
void gemm_bs(const __nv_bfloat16* __restrict__ Ah, const __nv_bfloat16* __restrict__ Al,
             const __nv_bfloat16* __restrict__ Bh, const __nv_bfloat16* __restrict__ Bl,
             const float* __restrict__ bias, float* __restrict__ C,
             __nv_bfloat16* __restrict__ Ch, __nv_bfloat16* __restrict__ Cl, int N) {
    __shared__ __align__(16) __nv_bfloat16 sAh[128 * PITCH];
    __shared__ __align__(16) __nv_bfloat16 sAl[128 * PITCH];
    __shared__ __align__(16) __nv_bfloat16 sBh[128 * PITCH];
    __shared__ __align__(16) __nv_bfloat16 sBl[128 * PITCH];

    const int tid = threadIdx.x;
    const int lane = tid & 31;
    const int wid = tid >> 5;
    const int wm = wid & 1;
    const int wn = wid >> 1;
    const int bx = blockIdx.x;
    const int by = blockIdx.y;

    const __nv_bfloat16* Agh = Ah + (size_t)by * 128 * 256;
    const __nv_bfloat16* Agl = Al + (size_t)by * 128 * 256;
    const __nv_bfloat16* Bgh = Bh + (size_t)bx * 128 * 256;
    const __nv_bfloat16* Bgl = Bl + (size_t)bx * 128 * 256;

    float acc[4][4][4];
#pragma unroll
    for (int mt = 0; mt < 4; ++mt)
#pragma unroll
        for (int nt = 0; nt < 4; ++nt)
#pragma unroll
            for (int i = 0; i < 4; ++i) acc[mt][nt][i] = 0.0f;

    const uint32_t uAh = smem_u32(sAh), uAl = smem_u32(sAl);
    const uint32_t uBh = smem_u32(sBh), uBl = smem_u32(sBl);

    const uint32_t aoff =
        (uint32_t)((wm * 64 + (lane & 15)) * PITCH + ((lane & 16) ? 8 : 0)) * 2;
    const uint32_t boff =
        (uint32_t)((wn * 32 + (lane & 7) + ((lane & 16) ? 8 : 0)) * PITCH +
                   ((lane & 8) ? 8 : 0)) * 2;

#pragma unroll 1
    for (int kb = 0; kb < 8; ++kb) {
        __syncthreads();
#pragma unroll
        for (int i = 0; i < 2; ++i) {
            int slot = tid + i * 256;           // 0..511
            int row = slot >> 2;                // 0..127
            int c8 = (slot & 3) * 8;            // 0,8,16,24
            size_t g = (size_t)row * 256 + kb * 32 + c8;
            int so = row * PITCH + c8;
            *reinterpret_cast<uint4*>(&sAh[so]) =
                *reinterpret_cast<const uint4*>(Agh + g);
            *reinterpret_cast<uint4*>(&sAl[so]) =
                *reinterpret_cast<const uint4*>(Agl + g);
            *reinterpret_cast<uint4*>(&sBh[so]) =
                *reinterpret_cast<const uint4*>(Bgh + g);
            *reinterpret_cast<uint4*>(&sBl[so]) =
                *reinterpret_cast<const uint4*>(Bgl + g);
        }
        __syncthreads();

#pragma unroll
        for (int kk = 0; kk < 2; ++kk) {
            const uint32_t kof = (uint32_t)(kk * 16) * 2;
            uint32_t bhf[2][4], blf[2][4];
#pragma unroll
            for (int ntp = 0; ntp < 2; ++ntp) {
                uint32_t ba = boff + (uint32_t)(ntp * 16 * PITCH) * 2 + kof;
                LDSM_X4(bhf[ntp][0], bhf[ntp][1], bhf[ntp][2], bhf[ntp][3], uBh + ba);
                LDSM_X4(blf[ntp][0], blf[ntp][1], blf[ntp][2], blf[ntp][3], uBl + ba);
            }
#pragma unroll
            for (int mt = 0; mt < 4; ++mt) {
                uint32_t aa = aoff + (uint32_t)(mt * 16 * PITCH) * 2 + kof;
                uint32_t ah0, ah1, ah2, ah3, al0, al1, al2, al3;
                LDSM_X4(ah0, ah1, ah2, ah3, uAh + aa);
                LDSM_X4(al0, al1, al2, al3, uAl + aa);
#pragma unroll
                for (int nt = 0; nt < 4; ++nt) {
                    const int ntp = nt >> 1;
                    const int hb = (nt & 1) * 2;
                    MMA_BF16(acc[mt][nt], ah0, ah1, ah2, ah3,
                             bhf[ntp][hb], bhf[ntp][hb + 1]);
                    MMA_BF16(acc[mt][nt], ah0, ah1, ah2, ah3,
                             blf[ntp][hb], blf[ntp][hb + 1]);
                    MMA_BF16(acc[mt][nt], al0, al1, al2, al3,
                             bhf[ntp][hb], bhf[ntp][hb + 1]);
                }
            }
        }
    }

    const int gid = lane >> 2;
    const int tig = lane & 3;
#pragma unroll
    for (int mt = 0; mt < 4; ++mt) {
        int row = by * 128 + wm * 64 + mt * 16 + gid;
#pragma unroll
        for (int nt = 0; nt < 4; ++nt) {
            int col = bx * 128 + wn * 32 + nt * 8 + 2 * tig;
            float2 v0 = make_float2(acc[mt][nt][0], acc[mt][nt][1]);
            float2 v1 = make_float2(acc[mt][nt][2], acc[mt][nt][3]);
            if (SPLIT_OUT) {
                __nv_bfloat162 h, l;
                split2(v0.x, v0.y, h, l);
                *reinterpret_cast<uint32_t*>(Ch + (size_t)row * N + col) = u32of(h);
                *reinterpret_cast<uint32_t*>(Cl + (size_t)row * N + col) = u32of(l);
                split2(v1.x, v1.y, h, l);
                *reinterpret_cast<uint32_t*>(Ch + (size_t)(row + 8) * N + col) = u32of(h);
                *reinterpret_cast<uint32_t*>(Cl + (size_t)(row + 8) * N + col) = u32of(l);
            } else {
                if (HAS_BIAS) {
                    float2 bb = *reinterpret_cast<const float2*>(bias + col);
                    v0.x += bb.x; v0.y += bb.y;
                    v1.x += bb.x; v1.y += bb.y;
                }
                *reinterpret_cast<float2*>(C + (size_t)row * N + col) = v0;
                *reinterpret_cast<float2*>(C + (size_t)(row + 8) * N + col) = v1;
            }
        }
    }
}

// ---------------------------------------------------------------------------
// tensor-core flash attention from pre-split bf16 qkv.
// block = 128 queries x (b,h). 8 warps; warp w owns rows w*16..w*16+15.
// V natural [j][d] in smem; PV B-fragments via ldmatrix.trans.
// Output written pre-split (hi/lo bf16) for the proj GEMM.
// ---------------------------------------------------------------------------
__global__ __launch_bounds__(256)
void attn_mma(const __nv_bfloat16* __restrict__ qkvh,
              const __nv_bfloat16* __restrict__ qkvl,
              const float* __restrict__ bias,
              __nv_bfloat16* __restrict__ outh,
              __nv_bfloat16* __restrict__ outl) {
    __shared__ __align__(16) __nv_bfloat16 Qh[128 * PITCH];
    __shared__ __align__(16) __nv_bfloat16 Ql[128 * PITCH];
    __shared__ __align__(16) __nv_bfloat16 Kh[64 * PITCH];
    __shared__ __align__(16) __nv_bfloat16 Kl[64 * PITCH];
    __shared__ __align__(16) __nv_bfloat16 Vh[64 * PITCH];
    __shared__ __align__(16) __nv_bfloat16 Vl[64 * PITCH];

    const int tid = threadIdx.x;
    const int lane = tid & 31;
    const int w = tid >> 5;
    const int gid = lane >> 2;
    const int tig = lane & 3;
    const int qc = blockIdx.x;
    const int h  = blockIdx.y;
    const int b  = blockIdx.z;

    const float scale = 0.17677669529663687f;   // 1/sqrt(32)
    const int qrow0 = b * N_ + qc * 128;

    // stage Q (128 rows x 32 bf16), straight copies
#pragma unroll
    for (int i = 0; i < 2; ++i) {
        int slot = tid + i * 256;
        int row = slot >> 2;
        int c8 = (slot & 3) * 8;
        size_t g = (size_t)(qrow0 + row) * 768 + h * HD_ + c8;
        int so = row * PITCH + c8;
        *reinterpret_cast<uint4*>(&Qh[so]) =
            *reinterpret_cast<const uint4*>(qkvh + g);
        *reinterpret_cast<uint4*>(&Ql[so]) =
            *reinterpret_cast<const uint4*>(qkvl + g);
    }
    __syncthreads();

    const uint32_t uQh = smem_u32(Qh), uQl = smem_u32(Ql);
    const uint32_t uKh = smem_u32(Kh), uKl = smem_u32(Kl);
    const uint32_t uVh = smem_u32(Vh), uVl = smem_u32(Vl);

    const uint32_t aoff =
        (uint32_t)((w * 16 + (lane & 15)) * PITCH + ((lane & 16) ? 8 : 0)) * 2;
    const uint32_t koff =
        (uint32_t)(((lane & 7) + ((lane & 16) ? 8 : 0)) * PITCH +
                   ((lane & 8) ? 8 : 0)) * 2;
    // trans-ldmatrix addressing for V[j][d]: rows j, col half by lane&16
    const uint32_t voff =
        (uint32_t)((lane & 15) * PITCH + ((lane & 16) ? 8 : 0)) * 2;

    // hoisted Q fragments (constant over key loop)
    uint32_t qh[2][4], ql[2][4];
#pragma unroll
    for (int kk = 0; kk < 2; ++kk) {
        const uint32_t kof = (uint32_t)(kk * 16) * 2;
        LDSM_X4(qh[kk][0], qh[kk][1], qh[kk][2], qh[kk][3], uQh + aoff + kof);
        LDSM_X4(ql[kk][0], ql[kk][1], ql[kk][2], ql[kk][3], uQl + aoff + kof);
    }

    float m0 = -1e30f, m1 = -1e30f, l0 = 0.0f, l1 = 0.0f;
    float oacc[4][4];
#pragma unroll
    for (int nt = 0; nt < 4; ++nt)
#pragma unroll
        for (int i = 0; i < 4; ++i) oacc[nt][i] = 0.0f;

    const int qi0 = qc * 128 + w * 16 + gid;
    const float* bias_b = bias + ((size_t)b << 20);

#pragma unroll 1
    for (int kt = 0; kt < 16; ++kt) {
        __syncthreads();
        const int krow0 = b * N_ + kt * 64;
        {
            int row = tid >> 2;                 // 0..63
            int c8 = (tid & 3) * 8;
            size_t g = (size_t)(krow0 + row) * 768 + 256 + h * HD_ + c8;
            int so = row * PITCH + c8;
            *reinterpret_cast<uint4*>(&Kh[so]) =
                *reinterpret_cast<const uint4*>(qkvh + g);
            *reinterpret_cast<uint4*>(&Kl[so]) =
                *reinterpret_cast<const uint4*>(qkvl + g);
            *reinterpret_cast<uint4*>(&Vh[so]) =
                *reinterpret_cast<const uint4*>(qkvh + g + 256);
            *reinterpret_cast<uint4*>(&Vl[so]) =
                *reinterpret_cast<const uint4*>(qkvl + g + 256);
        }
        __syncthreads();

        // ---- S = Q K^T (3-term split) ----
        float sacc[8][4];
#pragma unroll
        for (int nt = 0; nt < 8; ++nt)
#pragma unroll
            for (int i = 0; i < 4; ++i) sacc[nt][i] = 0.0f;

#pragma unroll
        for (int kk = 0; kk < 2; ++kk) {
            const uint32_t kof = (uint32_t)(kk * 16) * 2;
            uint32_t bh[4][4], bl[4][4];
#pragma unroll
            for (int ntp = 0; ntp < 4; ++ntp) {
                uint32_t ba = koff + (uint32_t)(ntp * 16 * PITCH) * 2 + kof;
                LDSM_X4(bh[ntp][0], bh[ntp][1], bh[ntp][2], bh[ntp][3], uKh + ba);
                LDSM_X4(bl[ntp][0], bl[ntp][1], bl[ntp][2], bl[ntp][3], uKl + ba);
            }
#pragma unroll
            for (int nt = 0; nt < 8; ++nt) {
                const int ntp = nt >> 1;
                const int hb = (nt & 1) * 2;
                MMA_BF16(sacc[nt], qh[kk][0], qh[kk][1], qh[kk][2], qh[kk][3],
                         bh[ntp][hb], bh[ntp][hb + 1]);
                MMA_BF16(sacc[nt], qh[kk][0], qh[kk][1], qh[kk][2], qh[kk][3],
                         bl[ntp][hb], bl[ntp][hb + 1]);
                MMA_BF16(sacc[nt], ql[kk][0], ql[kk][1], ql[kk][2], ql[kk][3],
                         bh[ntp][hb], bh[ntp][hb + 1]);
            }
        }

        // ---- scale + bias ----
#pragma unroll
        for (int nt = 0; nt < 8; ++nt) {
            int jc = kt * 64 + nt * 8 + 2 * tig;
            float2 bb0 = *reinterpret_cast<const float2*>(
                bias_b + (size_t)qi0 * 1024 + jc);
            float2 bb1 = *reinterpret_cast<const float2*>(
                bias_b + (size_t)(qi0 + 8) * 1024 + jc);
            sacc[nt][0] = fmaf(sacc[nt][0], scale, bb0.x);
            sacc[nt][1] = fmaf(sacc[nt][1], scale, bb0.y);
            sacc[nt][2] = fmaf(sacc[nt][2], scale, bb1.x);
            sacc[nt][3] = fmaf(sacc[nt][3], scale, bb1.y);
        }

        // ---- online softmax ----
        float mt0 = -1e30f, mt1 = -1e30f;
#pragma unroll
        for (int nt = 0; nt < 8; ++nt) {
            mt0 = fmaxf(mt0, fmaxf(sacc[nt][0], sacc[nt][1]));
            mt1 = fmaxf(mt1, fmaxf(sacc[nt][2], sacc[nt][3]));
        }
        mt0 = fmaxf(mt0, __shfl_xor_sync(0xffffffffu, mt0, 1));
        mt0 = fmaxf(mt0, __shfl_xor_sync(0xffffffffu, mt0, 2));
        mt1 = fmaxf(mt1, __shfl_xor_sync(0xffffffffu, mt1, 1));
        mt1 = fmaxf(mt1, __shfl_xor_sync(0xffffffffu, mt1, 2));
        float mn0 = fmaxf(m0, mt0), mn1 = fmaxf(m1, mt1);
        float sc0 = __expf(m0 - mn0), sc1 = __expf(m1 - mn1);
        float rs0 = 0.0f, rs1 = 0.0f;
#pragma unroll
        for (int nt = 0; nt < 8; ++nt) {
            sacc[nt][0] = __expf(sacc[nt][0] - mn0);
            sacc[nt][1] = __expf(sacc[nt][1] - mn0);
            sacc[nt][2] = __expf(sacc[nt][2] - mn1);
            sacc[nt][3] = __expf(sacc[nt][3] - mn1);
            rs0 += sacc[nt][0] + sacc[nt][1];
            rs1 += sacc[nt][2] + sacc[nt][3];
        }
        rs0 += __shfl_xor_sync(0xffffffffu, rs0, 1);
        rs0 += __shfl_xor_sync(0xffffffffu, rs0, 2);
        rs1 += __shfl_xor_sync(0xffffffffu, rs1, 1);
        rs1 += __shfl_xor_sync(0xffffffffu, rs1, 2);
        l0 = l0 * sc0 + rs0;
        l1 = l1 * sc1 + rs1;
        m0 = mn0; m1 = mn1;
#pragma unroll
        for (int nt = 0; nt < 4; ++nt) {
            oacc[nt][0] *= sc0; oacc[nt][1] *= sc0;
            oacc[nt][2] *= sc1; oacc[nt][3] *= sc1;
        }

        // ---- O += P V : P from registers; V via trans ldmatrix ----
#pragma unroll
        for (int ks = 0; ks < 4; ++ks) {
            __nv_bfloat162 hh, ll;
            uint32_t pah[4], pal[4];
            split2(sacc[2 * ks][0],     sacc[2 * ks][1],     hh, ll);
            pah[0] = u32of(hh); pal[0] = u32of(ll);
            split2(sacc[2 * ks][2],     sacc[2 * ks][3],     hh, ll);
            pah[1] = u32of(hh); pal[1] = u32of(ll);
            split2(sacc[2 * ks + 1][0], sacc[2 * ks + 1][1], hh, ll);
            pah[2] = u32of(hh); pal[2] = u32of(ll);
            split2(sacc[2 * ks + 1][2], sacc[2 * ks + 1][3], hh, ll);
            pah[3] = u32of(hh); pal[3] = u32of(ll);

            uint32_t vh[2][4], vl[2][4];
#pragma unroll
            for (int ntp = 0; ntp < 2; ++ntp) {
                uint32_t va = voff +
                    (uint32_t)(ks * 16 * PITCH + ntp * 16) * 2;
                LDSM_X4T(vh[ntp][0], vh[ntp][1], vh[ntp][2], vh[ntp][3], uVh + va);
                LDSM_X4T(vl[ntp][0], vl[ntp][1], vl[ntp][2], vl[ntp][3], uVl + va);
            }
#pragma unroll
            for (int nt = 0; nt < 4; ++nt) {
                const int ntp = nt >> 1;
                const int hb = (nt & 1) * 2;
                MMA_BF16(oacc[nt], pah[0], pah[1], pah[2], pah[3],
                         vh[ntp][hb], vh[ntp][hb + 1]);
                MMA_BF16(oacc[nt], pah[0], pah[1], pah[2], pah[3],
                         vl[ntp][hb], vl[ntp][hb + 1]);
                MMA_BF16(oacc[nt], pal[0], pal[1], pal[2], pal[3],
                         vh[ntp][hb], vh[ntp][hb + 1]);
            }
        }
    }

    // ---- epilogue: normalize + pre-split bf16 store ----
    const float inv0 = 1.0f / l0;
    const float inv1 = 1.0f / l1;
    const int row0 = qrow0 + w * 16 + gid;
#pragma unroll
    for (int nt = 0; nt < 4; ++nt) {
        int col = h * HD_ + nt * 8 + 2 * tig;
        __nv_bfloat162 hv, lv;
        split2(oacc[nt][0] * inv0, oacc[nt][1] * inv0, hv, lv);
        *reinterpret_cast<uint32_t*>(outh + (size_t)row0 * C_ + col) = u32of(hv);
        *reinterpret_cast<uint32_t*>(outl + (size_t)row0 * C_ + col) = u32of(lv);
        split2(oacc[nt][2] * inv1, oacc[nt][3] * inv1, hv, lv);
        *reinterpret_cast<uint32_t*>(outh + (size_t)(row0 + 8) * C_ + col) = u32of(hv);
        *reinterpret_cast<uint32_t*>(outl + (size_t)(row0 + 8) * C_ + col) = u32of(lv);
    }
}

// ---------------------------------------------------------------------------
// launch
// ---------------------------------------------------------------------------
extern "C" void kernel_launch(void* const* d_in, const int* in_sizes, int n_in,
                              void* d_out, int out_size) {
    const float* x     = (const float*)d_in[0];
    const float* elev  = (const float*)d_in[1];
    const float* uw    = (const float*)d_in[2];
    const float* vw    = (const float*)d_in[3];
    const float* wqkv  = (const float*)d_in[4];
    const float* wproj = (const float*)d_in[5];
    const float* bproj = (const float*)d_in[6];
    const float* alpha = (const float*)d_in[7];
    const float* beta  = (const float*)d_in[8];
    float* out = (float*)d_out;

    float *ws_p, *bias_p;
    __nv_bfloat16 *xh, *xl, *wqkvh, *wqkvl, *wprojh, *wprojl;
    __nv_bfloat16 *qkvh, *qkvl, *attnh, *attnl;
    cudaGetSymbolAddress((void**)&ws_p, g_ws);
    cudaGetSymbolAddress((void**)&bias_p, g_bias);
    cudaGetSymbolAddress((void**)&xh, g_xh);
    cudaGetSymbolAddress((void**)&xl, g_xl);
    cudaGetSymbolAddress((void**)&wqkvh, g_wqkvh);
    cudaGetSymbolAddress((void**)&wqkvl, g_wqkvl);
    cudaGetSymbolAddress((void**)&wprojh, g_wprojh);
    cudaGetSymbolAddress((void**)&wprojl, g_wprojl);
    cudaGetSymbolAddress((void**)&qkvh, g_qkvh);
    cudaGetSymbolAddress((void**)&qkvl, g_qkvl);
    cudaGetSymbolAddress((void**)&attnh, g_attnh);
    cudaGetSymbolAddress((void**)&attnl, g_attnl);

    // 1) wind strength + bias
    wind_kernel<<<32, 256>>>(uw, vw, ws_p);
    bias_kernel<<<B_ * N_, 256>>>(elev, ws_p, alpha, beta, bias_p);

    // 2) pre-split inputs to bf16 hi/lo
    convert_split<<<(B_ * N_ * C_ / 4 + 255) / 256, 256>>>(x, xh, xl,
                                                           B_ * N_ * C_ / 4);
    convert_split<<<(3 * C_ * C_ / 4 + 255) / 256, 256>>>(wqkv, wqkvh, wqkvl,
                                                          3 * C_ * C_ / 4);
    convert_split<<<(C_ * C_ / 4 + 255) / 256, 256>>>(wproj, wprojh, wprojl,
                                                      C_ * C_ / 4);

    // 3) qkv = x @ w_qkv^T (split output)
    gemm_bs<false, true><<<dim3(6, 64), 256>>>(
        xh, xl, wqkvh, wqkvl, nullptr, nullptr, qkvh, qkvl, 768);

    // 4) flash attention (split output)
    attn_mma<<<dim3(8, NH_, B_), 256>>>(qkvh, qkvl, bias_p, attnh, attnl);

    // 5) out = attn @ w_proj^T + b_proj (f32 output)
    gemm_bs<true, false><<<dim3(2, 64), 256>>>(
        attnh, attnl, wprojh, wprojl, bproj, out, nullptr, nullptr, 256);
}

// round 7
// speedup vs baseline: 3.2470x; 1.0795x over previous
#include <cuda_runtime.h>
#include <cuda_bf16.h>
#include <math.h>
#include <cstdint>

// ---------------------------------------------------------------------------
// PhysicsGuidedAttentionCorrected
// B=8, N=1024, C=256, NUM_HEADS=8, hd=32
// R7: cp.async double-buffered pipelines in attention + both GEMMs
//     (one sync per tile, load latency hidden); math identical to R6.
// ---------------------------------------------------------------------------

#define B_ 8
#define N_ 1024
#define C_ 256
#define NH_ 8
#define HD_ 32

// scratch (device globals; no allocations allowed)
__device__ float g_ws[B_ * N_];
__device__ float g_bias[B_ * N_ * N_];
__device__ __nv_bfloat16 g_xh[B_ * N_ * C_];
__device__ __nv_bfloat16 g_xl[B_ * N_ * C_];
__device__ __nv_bfloat16 g_wqkvh[3 * C_ * C_];
__device__ __nv_bfloat16 g_wqkvl[3 * C_ * C_];
__device__ __nv_bfloat16 g_wprojh[C_ * C_];
__device__ __nv_bfloat16 g_wprojl[C_ * C_];
__device__ __nv_bfloat16 g_qkvh[B_ * N_ * 3 * C_];
__device__ __nv_bfloat16 g_qkvl[B_ * N_ * 3 * C_];
__device__ __nv_bfloat16 g_attnh[B_ * N_ * C_];
__device__ __nv_bfloat16 g_attnl[B_ * N_ * C_];

// ---------------------------------------------------------------------------
// helpers
// ---------------------------------------------------------------------------
__device__ __forceinline__ uint32_t smem_u32(const void* p) {
    uint32_t a;
    asm("{ .reg .u64 t; cvta.to.shared.u64 t, %1; cvt.u32.u64 %0, t; }"
        : "=r"(a) : "l"(p));
    return a;
}

#define LDSM_X4(r0, r1, r2, r3, addr)                                        \
    asm volatile("ldmatrix.sync.aligned.m8n8.x4.shared.b16 {%0,%1,%2,%3}, [%4];" \
                 : "=r"(r0), "=r"(r1), "=r"(r2), "=r"(r3) : "r"(addr))

#define LDSM_X4T(r0, r1, r2, r3, addr)                                       \
    asm volatile("ldmatrix.sync.aligned.m8n8.x4.trans.shared.b16 {%0,%1,%2,%3}, [%4];" \
                 : "=r"(r0), "=r"(r1), "=r"(r2), "=r"(r3) : "r"(addr))

#define MMA_BF16(d, a0, a1, a2, a3, b0, b1)                                  \
    asm volatile("mma.sync.aligned.m16n8k16.row.col.f32.bf16.bf16.f32 "      \
                 "{%0,%1,%2,%3}, {%4,%5,%6,%7}, {%8,%9}, {%0,%1,%2,%3};"     \
                 : "+f"((d)[0]), "+f"((d)[1]), "+f"((d)[2]), "+f"((d)[3])    \
                 : "r"(a0), "r"(a1), "r"(a2), "r"(a3), "r"(b0), "r"(b1))

#define CP_ASYNC16(saddr, gptr)                                              \
    asm volatile("cp.async.cg.shared.global [%0], [%1], 16;"                 \
                 :: "r"(saddr), "l"(gptr))
#define CP_COMMIT() asm volatile("cp.async.commit_group;" ::: "memory")
#define CP_WAIT0()  asm volatile("cp.async.wait_group 0;" ::: "memory")

__device__ __forceinline__ void split2(float x, float y,
                                       __nv_bfloat162& hi, __nv_bfloat162& lo) {
    __nv_bfloat16 hx = __float2bfloat16_rn(x);
    __nv_bfloat16 hy = __float2bfloat16_rn(y);
    hi = __nv_bfloat162(hx, hy);
    lo = __nv_bfloat162(__float2bfloat16_rn(x - __bfloat162float(hx)),
                        __float2bfloat16_rn(y - __bfloat162float(hy)));
}
__device__ __forceinline__ uint32_t u32of(__nv_bfloat162 v) {
    return *reinterpret_cast<uint32_t*>(&v);
}

// ---------------------------------------------------------------------------
// wind strength
// ---------------------------------------------------------------------------
__global__ void wind_kernel(const float* __restrict__ u,
                            const float* __restrict__ v,
                            float* __restrict__ ws) {
    int t = blockIdx.x * blockDim.x + threadIdx.x;
    if (t >= B_ * N_) return;
    int b = t >> 10;
    int n = t & 1023;
    int r = n >> 5;
    int c = n & 31;
    const float* ub = u + b * 4096;
    const float* vb = v + b * 4096;
    float s = 0.0f;
#pragma unroll
    for (int dr = 0; dr < 2; ++dr)
#pragma unroll
        for (int dc = 0; dc < 2; ++dc) {
            int idx = (2 * r + dr) * 64 + (2 * c + dc);
            float uu = ub[idx], vv = vb[idx];
            s += sqrtf(uu * uu + vv * vv + 1e-8f);
        }
    ws[t] = s * 0.25f;
}

// ---------------------------------------------------------------------------
// bias precompute: bias[b,i,j] (head-independent)
// ---------------------------------------------------------------------------
__global__ __launch_bounds__(256)
void bias_kernel(const float* __restrict__ elev, const float* __restrict__ ws,
                 const float* __restrict__ alpha_p, const float* __restrict__ beta_p,
                 float* __restrict__ bias) {
    const int bi = blockIdx.x;
    const int b = bi >> 10;
    const float alpha = *alpha_p;
    const float beta = *beta_p;
    const float e_i = elev[bi];
    const float w_i = ws[bi];
    const float* ej = elev + b * 1024;
    const float* wj = ws + b * 1024;
    float* bp = bias + (size_t)bi * 1024;
    const int j4 = threadIdx.x * 4;
    float4 e = *reinterpret_cast<const float4*>(ej + j4);
    float4 w = *reinterpret_cast<const float4*>(wj + j4);
    float4 o;
#pragma unroll
    for (int k = 0; k < 4; ++k) {
        float evk = (&e.x)[k], wvk = (&w.x)[k];
        float ed = fmaxf((evk - e_i) * 1e-3f, 0.0f);
        float z = (w_i + wvk) * 0.5f - 5.0f;
        float wf = 1.0f / (1.0f + __expf(-z));
        float bia = -alpha * ed * (1.0f - beta * wf);
        (&o.x)[k] = fminf(fmaxf(bia, -10.0f), 0.0f);
    }
    *reinterpret_cast<float4*>(bp + j4) = o;
}

// ---------------------------------------------------------------------------
// fp32 -> bf16 hi/lo split converter
// ---------------------------------------------------------------------------
__global__ void convert_split(const float* __restrict__ in,
                              __nv_bfloat16* __restrict__ hi,
                              __nv_bfloat16* __restrict__ lo, int n4) {
    int i = blockIdx.x * blockDim.x + threadIdx.x;
    if (i >= n4) return;
    float4 v = reinterpret_cast<const float4*>(in)[i];
    __nv_bfloat162 h01, l01, h23, l23;
    split2(v.x, v.y, h01, l01);
    split2(v.z, v.w, h23, l23);
    uint2 hv = make_uint2(u32of(h01), u32of(h23));
    uint2 lv = make_uint2(u32of(l01), u32of(l23));
    *reinterpret_cast<uint2*>(hi + 4 * i) = hv;
    *reinterpret_cast<uint2*>(lo + 4 * i) = lv;
}

// ---------------------------------------------------------------------------
// bf16-split tensor-core GEMM, cp.async double-buffered.
// C[m,n] = sum_k A[m,k]*B[n,k]; K=256; CTA 128x128; 8 warps (2M x 4N).
// dynamic smem: 2 buffers x {Ah, Al, Bh, Bl} each 128x40 bf16
// ---------------------------------------------------------------------------
#define PITCH 40
#define GEMM_BUF_BYTES (4 * 128 * PITCH * 2)     // 40960 per buffer
#define GEMM_SMEM_BYTES (2 * GEMM_BUF_BYTES)     // 81920

template <bool HAS_BIAS, bool SPLIT_OUT>
__global__ __launch_bounds__(256, 2)
void gemm_bs(const __nv_bfloat16* __restrict__ Ah, const __nv_bfloat16* __restrict__ Al,
             const __nv_bfloat16* __restrict__ Bh, const __nv_bfloat16* __restrict__ Bl,
             const float* __restrict__ bias, float* __restrict__ C,
             __nv_bfloat16* __restrict__ Ch, __nv_bfloat16* __restrict__ Cl, int N) {
    extern __shared__ __align__(16) char smem_raw[];
    const uint32_t uS = smem_u32(smem_raw);

    const int tid = threadIdx.x;
    const int lane = tid & 31;
    const int wid = tid >> 5;
    const int wm = wid & 1;
    const int wn = wid >> 1;
    const int bx = blockIdx.x;
    const int by = blockIdx.y;

    const __nv_bfloat16* Agh = Ah + (size_t)by * 128 * 256;
    const __nv_bfloat16* Agl = Al + (size_t)by * 128 * 256;
    const __nv_bfloat16* Bgh = Bh + (size_t)bx * 128 * 256;
    const __nv_bfloat16* Bgl = Bl + (size_t)bx * 128 * 256;

    float acc[4][4][4];
#pragma unroll
    for (int mt = 0; mt < 4; ++mt)
#pragma unroll
        for (int nt = 0; nt < 4; ++nt)
#pragma unroll
            for (int i = 0; i < 4; ++i) acc[mt][nt][i] = 0.0f;

    const uint32_t aoff =
        (uint32_t)((wm * 64 + (lane & 15)) * PITCH + ((lane & 16) ? 8 : 0)) * 2;
    const uint32_t boff =
        (uint32_t)((wn * 32 + (lane & 7) + ((lane & 16) ? 8 : 0)) * PITCH +
                   ((lane & 8) ? 8 : 0)) * 2;

    // staging geometry: 2 slots/thread, 4 arrays each
    const int row0 = tid >> 2;                  // 0..63 (slot i adds 64)
    const int c8 = (tid & 3) * 8;

    // prologue: stage kb=0 into buffer 0
#pragma unroll
    for (int i = 0; i < 2; ++i) {
        int row = row0 + i * 64;
        size_t g = (size_t)row * 256 + c8;
        uint32_t so = (uint32_t)(row * PITCH + c8) * 2;
        CP_ASYNC16(uS + so, Agh + g);
        CP_ASYNC16(uS + 10240 + so, Agl + g);
        CP_ASYNC16(uS + 20480 + so, Bgh + g);
        CP_ASYNC16(uS + 30720 + so, Bgl + g);
    }
    CP_COMMIT();
    CP_WAIT0();
    __syncthreads();

#pragma unroll 1
    for (int kb = 0; kb < 8; ++kb) {
        const int p = kb & 1;
        const uint32_t bufb = uS + (uint32_t)p * GEMM_BUF_BYTES;

        if (kb < 7) {
            const uint32_t nb = uS + (uint32_t)(1 - p) * GEMM_BUF_BYTES;
#pragma unroll
            for (int i = 0; i < 2; ++i) {
                int row = row0 + i * 64;
                size_t g = (size_t)row * 256 + (kb + 1) * 32 + c8;
                uint32_t so = (uint32_t)(row * PITCH + c8) * 2;
                CP_ASYNC16(nb + so, Agh + g);
                CP_ASYNC16(nb + 10240 + so, Agl + g);
                CP_ASYNC16(nb + 20480 + so, Bgh + g);
                CP_ASYNC16(nb + 30720 + so, Bgl + g);
            }
            CP_COMMIT();
        }

        const uint32_t uAh = bufb, uAl = bufb + 10240;
        const uint32_t uBh = bufb + 20480, uBl = bufb + 30720;

#pragma unroll
        for (int kk = 0; kk < 2; ++kk) {
            const uint32_t kof = (uint32_t)(kk * 16) * 2;
            uint32_t bhf[2][4], blf[2][4];
#pragma unroll
            for (int ntp = 0; ntp < 2; ++ntp) {
                uint32_t ba = boff + (uint32_t)(ntp * 16 * PITCH) * 2 + kof;
                LDSM_X4(bhf[ntp][0], bhf[ntp][1], bhf[ntp][2], bhf[ntp][3], uBh + ba);
                LDSM_X4(blf[ntp][0], blf[ntp][1], blf[ntp][2], blf[ntp][3], uBl + ba);
            }
#pragma unroll
            for (int mt = 0; mt < 4; ++mt) {
                uint32_t aa = aoff + (uint32_t)(mt * 16 * PITCH) * 2 + kof;
                uint32_t ah0, ah1, ah2, ah3, al0, al1, al2, al3;
                LDSM_X4(ah0, ah1, ah2, ah3, uAh + aa);
                LDSM_X4(al0, al1, al2, al3, uAl + aa);
#pragma unroll
                for (int nt = 0; nt < 4; ++nt) {
                    const int ntp = nt >> 1;
                    const int hb = (nt & 1) * 2;
                    MMA_BF16(acc[mt][nt], ah0, ah1, ah2, ah3,
                             bhf[ntp][hb], bhf[ntp][hb + 1]);
                    MMA_BF16(acc[mt][nt], ah0, ah1, ah2, ah3,
                             blf[ntp][hb], blf[ntp][hb + 1]);
                    MMA_BF16(acc[mt][nt], al0, al1, al2, al3,
                             bhf[ntp][hb], bhf[ntp][hb + 1]);
                }
            }
        }

        if (kb < 7) CP_WAIT0();
        __syncthreads();
    }

    const int gid = lane >> 2;
    const int tig = lane & 3;
#pragma unroll
    for (int mt = 0; mt < 4; ++mt) {
        int row = by * 128 + wm * 64 + mt * 16 + gid;
#pragma unroll
        for (int nt = 0; nt < 4; ++nt) {
            int col = bx * 128 + wn * 32 + nt * 8 + 2 * tig;
            float2 v0 = make_float2(acc[mt][nt][0], acc[mt][nt][1]);
            float2 v1 = make_float2(acc[mt][nt][2], acc[mt][nt][3]);
            if (SPLIT_OUT) {
                __nv_bfloat162 h, l;
                split2(v0.x, v0.y, h, l);
                *reinterpret_cast<uint32_t*>(Ch + (size_t)row * N + col) = u32of(h);
                *reinterpret_cast<uint32_t*>(Cl + (size_t)row * N + col) = u32of(l);
                split2(v1.x, v1.y, h, l);
                *reinterpret_cast<uint32_t*>(Ch + (size_t)(row + 8) * N + col) = u32of(h);
                *reinterpret_cast<uint32_t*>(Cl + (size_t)(row + 8) * N + col) = u32of(l);
            } else {
                if (HAS_BIAS) {
                    float2 bb = *reinterpret_cast<const float2*>(bias + col);
                    v0.x += bb.x; v0.y += bb.y;
                    v1.x += bb.x; v1.y += bb.y;
                }
                *reinterpret_cast<float2*>(C + (size_t)row * N + col) = v0;
                *reinterpret_cast<float2*>(C + (size_t)(row + 8) * N + col) = v1;
            }
        }
    }
}

// ---------------------------------------------------------------------------
// tensor-core flash attention, cp.async double-buffered K/V.
// block = 128 queries x (b,h). 8 warps; warp w owns rows w*16..w*16+15.
// dynamic smem: Qh|Ql (128x40 each) + 2 buffers x {Kh,Kl,Vh,Vl} (64x40 each)
// ---------------------------------------------------------------------------
#define ATTN_Q_BYTES (2 * 128 * PITCH * 2)       // 20480
#define ATTN_BUF_BYTES (4 * 64 * PITCH * 2)      // 20480 per buffer
#define ATTN_SMEM_BYTES (ATTN_Q_BYTES + 2 * ATTN_BUF_BYTES)   // 61440

__global__ __launch_bounds__(256, 2)
void attn_mma(const __nv_bfloat16* __restrict__ qkvh,
              const __nv_bfloat16* __restrict__ qkvl,
              const float* __restrict__ bias,
              __nv_bfloat16* __restrict__ outh,
              __nv_bfloat16* __restrict__ outl) {
    extern __shared__ __align__(16) char smem_raw[];
    __nv_bfloat16* Qh = reinterpret_cast<__nv_bfloat16*>(smem_raw);
    __nv_bfloat16* Ql = Qh + 128 * PITCH;
    const uint32_t uQh = smem_u32(Qh);
    const uint32_t uQl = uQh + 128 * PITCH * 2;
    const uint32_t uKV = uQl + 128 * PITCH * 2;   // 2 x 20480 bytes

    const int tid = threadIdx.x;
    const int lane = tid & 31;
    const int w = tid >> 5;
    const int gid = lane >> 2;
    const int tig = lane & 3;
    const int qc = blockIdx.x;
    const int h  = blockIdx.y;
    const int b  = blockIdx.z;

    const float scale = 0.17677669529663687f;   // 1/sqrt(32)
    const int qrow0 = b * N_ + qc * 128;

    // staging geometry for K/V tiles (one slot per thread)
    const int krow = tid >> 2;                  // 0..63
    const int kc8 = (tid & 3) * 8;
    const uint32_t kso = (uint32_t)(krow * PITCH + kc8) * 2;

    // prologue: stage kt=0 into buffer 0
    {
        size_t g = (size_t)(b * N_ + krow) * 768 + 256 + h * HD_ + kc8;
        CP_ASYNC16(uKV + kso, qkvh + g);
        CP_ASYNC16(uKV + 5120 + kso, qkvl + g);
        CP_ASYNC16(uKV + 10240 + kso, qkvh + g + 256);
        CP_ASYNC16(uKV + 15360 + kso, qkvl + g + 256);
        CP_COMMIT();
    }

    // stage Q (regular stores)
#pragma unroll
    for (int i = 0; i < 2; ++i) {
        int slot = tid + i * 256;
        int row = slot >> 2;
        int c8 = (slot & 3) * 8;
        size_t g = (size_t)(qrow0 + row) * 768 + h * HD_ + c8;
        int so = row * PITCH + c8;
        *reinterpret_cast<uint4*>(&Qh[so]) =
            *reinterpret_cast<const uint4*>(qkvh + g);
        *reinterpret_cast<uint4*>(&Ql[so]) =
            *reinterpret_cast<const uint4*>(qkvl + g);
    }
    CP_WAIT0();
    __syncthreads();

    const uint32_t aoff =
        (uint32_t)((w * 16 + (lane & 15)) * PITCH + ((lane & 16) ? 8 : 0)) * 2;
    const uint32_t koff =
        (uint32_t)(((lane & 7) + ((lane & 16) ? 8 : 0)) * PITCH +
                   ((lane & 8) ? 8 : 0)) * 2;
    const uint32_t voff =
        (uint32_t)((lane & 15) * PITCH + ((lane & 16) ? 8 : 0)) * 2;

    // hoisted Q fragments
    uint32_t qh[2][4], ql[2][4];
#pragma unroll
    for (int kk = 0; kk < 2; ++kk) {
        const uint32_t kof = (uint32_t)(kk * 16) * 2;
        LDSM_X4(qh[kk][0], qh[kk][1], qh[kk][2], qh[kk][3], uQh + aoff + kof);
        LDSM_X4(ql[kk][0], ql[kk][1], ql[kk][2], ql[kk][3], uQl + aoff + kof);
    }

    float m0 = -1e30f, m1 = -1e30f, l0 = 0.0f, l1 = 0.0f;
    float oacc[4][4];
#pragma unroll
    for (int nt = 0; nt < 4; ++nt)
#pragma unroll
        for (int i = 0; i < 4; ++i) oacc[nt][i] = 0.0f;

    const int qi0 = qc * 128 + w * 16 + gid;
    const float* bias_b = bias + ((size_t)b << 20);

#pragma unroll 1
    for (int kt = 0; kt < 16; ++kt) {
        const int p = kt & 1;
        const uint32_t bufb = uKV + (uint32_t)p * ATTN_BUF_BYTES;

        if (kt < 15) {
            const uint32_t nb = uKV + (uint32_t)(1 - p) * ATTN_BUF_BYTES;
            size_t g = (size_t)(b * N_ + (kt + 1) * 64 + krow) * 768 + 256 +
                       h * HD_ + kc8;
            CP_ASYNC16(nb + kso, qkvh + g);
            CP_ASYNC16(nb + 5120 + kso, qkvl + g);
            CP_ASYNC16(nb + 10240 + kso, qkvh + g + 256);
            CP_ASYNC16(nb + 15360 + kso, qkvl + g + 256);
            CP_COMMIT();
        }

        const uint32_t uKh = bufb, uKl = bufb + 5120;
        const uint32_t uVh = bufb + 10240, uVl = bufb + 15360;

        // ---- S = Q K^T (3-term split) ----
        float sacc[8][4];
#pragma unroll
        for (int nt = 0; nt < 8; ++nt)
#pragma unroll
            for (int i = 0; i < 4; ++i) sacc[nt][i] = 0.0f;

#pragma unroll
        for (int kk = 0; kk < 2; ++kk) {
            const uint32_t kof = (uint32_t)(kk * 16) * 2;
            uint32_t bh[4][4], bl[4][4];
#pragma unroll
            for (int ntp = 0; ntp < 4; ++ntp) {
                uint32_t ba = koff + (uint32_t)(ntp * 16 * PITCH) * 2 + kof;
                LDSM_X4(bh[ntp][0], bh[ntp][1], bh[ntp][2], bh[ntp][3], uKh + ba);
                LDSM_X4(bl[ntp][0], bl[ntp][1], bl[ntp][2], bl[ntp][3], uKl + ba);
            }
#pragma unroll
            for (int nt = 0; nt < 8; ++nt) {
                const int ntp = nt >> 1;
                const int hb = (nt & 1) * 2;
                MMA_BF16(sacc[nt], qh[kk][0], qh[kk][1], qh[kk][2], qh[kk][3],
                         bh[ntp][hb], bh[ntp][hb + 1]);
                MMA_BF16(sacc[nt], qh[kk][0], qh[kk][1], qh[kk][2], qh[kk][3],
                         bl[ntp][hb], bl[ntp][hb + 1]);
                MMA_BF16(sacc[nt], ql[kk][0], ql[kk][1], ql[kk][2], ql[kk][3],
                         bh[ntp][hb], bh[ntp][hb + 1]);
            }
        }

        // ---- scale + bias ----
#pragma unroll
        for (int nt = 0; nt < 8; ++nt) {
            int jc = kt * 64 + nt * 8 + 2 * tig;
            float2 bb0 = *reinterpret_cast<const float2*>(
                bias_b + (size_t)qi0 * 1024 + jc);
            float2 bb1 = *reinterpret_cast<const float2*>(
                bias_b + (size_t)(qi0 + 8) * 1024 + jc);
            sacc[nt][0] = fmaf(sacc[nt][0], scale, bb0.x);
            sacc[nt][1] = fmaf(sacc[nt][1], scale, bb0.y);
            sacc[nt][2] = fmaf(sacc[nt][2], scale, bb1.x);
            sacc[nt][3] = fmaf(sacc[nt][3], scale, bb1.y);
        }

        // ---- online softmax ----
        float mt0 = -1e30f, mt1 = -1e30f;
#pragma unroll
        for (int nt = 0; nt < 8; ++nt) {
            mt0 = fmaxf(mt0, fmaxf(sacc[nt][0], sacc[nt][1]));
            mt1 = fmaxf(mt1, fmaxf(sacc[nt][2], sacc[nt][3]));
        }
        mt0 = fmaxf(mt0, __shfl_xor_sync(0xffffffffu, mt0, 1));
        mt0 = fmaxf(mt0, __shfl_xor_sync(0xffffffffu, mt0, 2));
        mt1 = fmaxf(mt1, __shfl_xor_sync(0xffffffffu, mt1, 1));
        mt1 = fmaxf(mt1, __shfl_xor_sync(0xffffffffu, mt1, 2));
        float mn0 = fmaxf(m0, mt0), mn1 = fmaxf(m1, mt1);
        float sc0 = __expf(m0 - mn0), sc1 = __expf(m1 - mn1);
        float rs0 = 0.0f, rs1 = 0.0f;
#pragma unroll
        for (int nt = 0; nt < 8; ++nt) {
            sacc[nt][0] = __expf(sacc[nt][0] - mn0);
            sacc[nt][1] = __expf(sacc[nt][1] - mn0);
            sacc[nt][2] = __expf(sacc[nt][2] - mn1);
            sacc[nt][3] = __expf(sacc[nt][3] - mn1);
            rs0 += sacc[nt][0] + sacc[nt][1];
            rs1 += sacc[nt][2] + sacc[nt][3];
        }
        rs0 += __shfl_xor_sync(0xffffffffu, rs0, 1);
        rs0 += __shfl_xor_sync(0xffffffffu, rs0, 2);
        rs1 += __shfl_xor_sync(0xffffffffu, rs1, 1);
        rs1 += __shfl_xor_sync(0xffffffffu, rs1, 2);
        l0 = l0 * sc0 + rs0;
        l1 = l1 * sc1 + rs1;
        m0 = mn0; m1 = mn1;
#pragma unroll
        for (int nt = 0; nt < 4; ++nt) {
            oacc[nt][0] *= sc0; oacc[nt][1] *= sc0;
            oacc[nt][2] *= sc1; oacc[nt][3] *= sc1;
        }

        // ---- O += P V ----
#pragma unroll
        for (int ks = 0; ks < 4; ++ks) {
            __nv_bfloat162 hh, ll;
            uint32_t pah[4], pal[4];
            split2(sacc[2 * ks][0],     sacc[2 * ks][1],     hh, ll);
            pah[0] = u32of(hh); pal[0] = u32of(ll);
            split2(sacc[2 * ks][2],     sacc[2 * ks][3],     hh, ll);
            pah[1] = u32of(hh); pal[1] = u32of(ll);
            split2(sacc[2 * ks + 1][0], sacc[2 * ks + 1][1], hh, ll);
            pah[2] = u32of(hh); pal[2] = u32of(ll);
            split2(sacc[2 * ks + 1][2], sacc[2 * ks + 1][3], hh, ll);
            pah[3] = u32of(hh); pal[3] = u32of(ll);

            uint32_t vh[2][4], vl[2][4];
#pragma unroll
            for (int ntp = 0; ntp < 2; ++ntp) {
                uint32_t va = voff + (uint32_t)(ks * 16 * PITCH + ntp * 16) * 2;
                LDSM_X4T(vh[ntp][0], vh[ntp][1], vh[ntp][2], vh[ntp][3], uVh + va);
                LDSM_X4T(vl[ntp][0], vl[ntp][1], vl[ntp][2], vl[ntp][3], uVl + va);
            }
#pragma unroll
            for (int nt = 0; nt < 4; ++nt) {
                const int ntp = nt >> 1;
                const int hb = (nt & 1) * 2;
                MMA_BF16(oacc[nt], pah[0], pah[1], pah[2], pah[3],
                         vh[ntp][hb], vh[ntp][hb + 1]);
                MMA_BF16(oacc[nt], pah[0], pah[1], pah[2], pah[3],
                         vl[ntp][hb], vl[ntp][hb + 1]);
                MMA_BF16(oacc[nt], pal[0], pal[1], pal[2], pal[3],
                         vh[ntp][hb], vh[ntp][hb + 1]);
            }
        }

        if (kt < 15) CP_WAIT0();
        __syncthreads();
    }

    // ---- epilogue ----
    const float inv0 = 1.0f / l0;
    const float inv1 = 1.0f / l1;
    const int row0 = qrow0 + w * 16 + gid;
#pragma unroll
    for (int nt = 0; nt < 4; ++nt) {
        int col = h * HD_ + nt * 8 + 2 * tig;
        __nv_bfloat162 hv, lv;
        split2(oacc[nt][0] * inv0, oacc[nt][1] * inv0, hv, lv);
        *reinterpret_cast<uint32_t*>(outh + (size_t)row0 * C_ + col) = u32of(hv);
        *reinterpret_cast<uint32_t*>(outl + (size_t)row0 * C_ + col) = u32of(lv);
        split2(oacc[nt][2] * inv1, oacc[nt][3] * inv1, hv, lv);
        *reinterpret_cast<uint32_t*>(outh + (size_t)(row0 + 8) * C_ + col) = u32of(hv);
        *reinterpret_cast<uint32_t*>(outl + (size_t)(row0 + 8) * C_ + col) = u32of(lv);
    }
}

// ---------------------------------------------------------------------------
// launch
// ---------------------------------------------------------------------------
extern "C" void kernel_launch(void* const* d_in, const int* in_sizes, int n_in,
                              void* d_out, int out_size) {
    const float* x     = (const float*)d_in[0];
    const float* elev  = (const float*)d_in[1];
    const float* uw    = (const float*)d_in[2];
    const float* vw    = (const float*)d_in[3];
    const float* wqkv  = (const float*)d_in[4];
    const float* wproj = (const float*)d_in[5];
    const float* bproj = (const float*)d_in[6];
    const float* alpha = (const float*)d_in[7];
    const float* beta  = (const float*)d_in[8];
    float* out = (float*)d_out;

    float *ws_p, *bias_p;
    __nv_bfloat16 *xh, *xl, *wqkvh, *wqkvl, *wprojh, *wprojl;
    __nv_bfloat16 *qkvh, *qkvl, *attnh, *attnl;
    cudaGetSymbolAddress((void**)&ws_p, g_ws);
    cudaGetSymbolAddress((void**)&bias_p, g_bias);
    cudaGetSymbolAddress((void**)&xh, g_xh);
    cudaGetSymbolAddress((void**)&xl, g_xl);
    cudaGetSymbolAddress((void**)&wqkvh, g_wqkvh);
    cudaGetSymbolAddress((void**)&wqkvl, g_wqkvl);
    cudaGetSymbolAddress((void**)&wprojh, g_wprojh);
    cudaGetSymbolAddress((void**)&wprojl, g_wprojl);
    cudaGetSymbolAddress((void**)&qkvh, g_qkvh);
    cudaGetSymbolAddress((void**)&qkvl, g_qkvl);
    cudaGetSymbolAddress((void**)&attnh, g_attnh);
    cudaGetSymbolAddress((void**)&attnl, g_attnl);

    cudaFuncSetAttribute(gemm_bs<false, true>,
                         cudaFuncAttributeMaxDynamicSharedMemorySize,
                         GEMM_SMEM_BYTES);
    cudaFuncSetAttribute(gemm_bs<true, false>,
                         cudaFuncAttributeMaxDynamicSharedMemorySize,
                         GEMM_SMEM_BYTES);
    cudaFuncSetAttribute(attn_mma,
                         cudaFuncAttributeMaxDynamicSharedMemorySize,
                         ATTN_SMEM_BYTES);

    // 1) wind strength + bias
    wind_kernel<<<32, 256>>>(uw, vw, ws_p);
    bias_kernel<<<B_ * N_, 256>>>(elev, ws_p, alpha, beta, bias_p);

    // 2) pre-split inputs to bf16 hi/lo
    convert_split<<<(B_ * N_ * C_ / 4 + 255) / 256, 256>>>(x, xh, xl,
                                                           B_ * N_ * C_ / 4);
    convert_split<<<(3 * C_ * C_ / 4 + 255) / 256, 256>>>(wqkv, wqkvh, wqkvl,
                                                          3 * C_ * C_ / 4);
    convert_split<<<(C_ * C_ / 4 + 255) / 256, 256>>>(wproj, wprojh, wprojl,
                                                      C_ * C_ / 4);

    // 3) qkv = x @ w_qkv^T (split output)
    gemm_bs<false, true><<<dim3(6, 64), 256, GEMM_SMEM_BYTES>>>(
        xh, xl, wqkvh, wqkvl, nullptr, nullptr, qkvh, qkvl, 768);

    // 4) flash attention (split output)
    attn_mma<<<dim3(8, NH_, B_), 256, ATTN_SMEM_BYTES>>>(
        qkvh, qkvl, bias_p, attnh, attnl);

    // 5) out = attn @ w_proj^T + b_proj (f32 output)
    gemm_bs<true, false><<<dim3(2, 64), 256, GEMM_SMEM_BYTES>>>(
        attnh, attnl, wprojh, wprojl, bproj, out, nullptr, nullptr, 256);
}

// round 8
// speedup vs baseline: 3.4297x; 1.0563x over previous
#include <cuda_runtime.h>
#include <cuda_bf16.h>
#include <math.h>
#include <cstdint>

// ---------------------------------------------------------------------------
// PhysicsGuidedAttentionCorrected
// B=8, N=1024, C=256, NUM_HEADS=8, hd=32
// R8: bias precomputed in MMA-fragment order (attn reads coalesced LDG.128);
//     merged convert kernel; rest identical to R7 (cp.async pipelines).
// ---------------------------------------------------------------------------

#define B_ 8
#define N_ 1024
#define C_ 256
#define NH_ 8
#define HD_ 32

// scratch (device globals; no allocations allowed)
__device__ float g_ws[B_ * N_];
__device__ float4 g_bias4[B_ * N_ * N_ / 4];       // fragment-ordered bias
__device__ __nv_bfloat16 g_xh[B_ * N_ * C_];
__device__ __nv_bfloat16 g_xl[B_ * N_ * C_];
__device__ __nv_bfloat16 g_wqkvh[3 * C_ * C_];
__device__ __nv_bfloat16 g_wqkvl[3 * C_ * C_];
__device__ __nv_bfloat16 g_wprojh[C_ * C_];
__device__ __nv_bfloat16 g_wprojl[C_ * C_];
__device__ __nv_bfloat16 g_qkvh[B_ * N_ * 3 * C_];
__device__ __nv_bfloat16 g_qkvl[B_ * N_ * 3 * C_];
__device__ __nv_bfloat16 g_attnh[B_ * N_ * C_];
__device__ __nv_bfloat16 g_attnl[B_ * N_ * C_];

// ---------------------------------------------------------------------------
// helpers
// ---------------------------------------------------------------------------
__device__ __forceinline__ uint32_t smem_u32(const void* p) {
    uint32_t a;
    asm("{ .reg .u64 t; cvta.to.shared.u64 t, %1; cvt.u32.u64 %0, t; }"
        : "=r"(a) : "l"(p));
    return a;
}

#define LDSM_X4(r0, r1, r2, r3, addr)                                        \
    asm volatile("ldmatrix.sync.aligned.m8n8.x4.shared.b16 {%0,%1,%2,%3}, [%4];" \
                 : "=r"(r0), "=r"(r1), "=r"(r2), "=r"(r3) : "r"(addr))

#define LDSM_X4T(r0, r1, r2, r3, addr)                                       \
    asm volatile("ldmatrix.sync.aligned.m8n8.x4.trans.shared.b16 {%0,%1,%2,%3}, [%4];" \
                 : "=r"(r0), "=r"(r1), "=r"(r2), "=r"(r3) : "r"(addr))

#define MMA_BF16(d, a0, a1, a2, a3, b0, b1)                                  \
    asm volatile("mma.sync.aligned.m16n8k16.row.col.f32.bf16.bf16.f32 "      \
                 "{%0,%1,%2,%3}, {%4,%5,%6,%7}, {%8,%9}, {%0,%1,%2,%3};"     \
                 : "+f"((d)[0]), "+f"((d)[1]), "+f"((d)[2]), "+f"((d)[3])    \
                 : "r"(a0), "r"(a1), "r"(a2), "r"(a3), "r"(b0), "r"(b1))

#define CP_ASYNC16(saddr, gptr)                                              \
    asm volatile("cp.async.cg.shared.global [%0], [%1], 16;"                 \
                 :: "r"(saddr), "l"(gptr))
#define CP_COMMIT() asm volatile("cp.async.commit_group;" ::: "memory")
#define CP_WAIT0()  asm volatile("cp.async.wait_group 0;" ::: "memory")

__device__ __forceinline__ void split2(float x, float y,
                                       __nv_bfloat162& hi, __nv_bfloat162& lo) {
    __nv_bfloat16 hx = __float2bfloat16_rn(x);
    __nv_bfloat16 hy = __float2bfloat16_rn(y);
    hi = __nv_bfloat162(hx, hy);
    lo = __nv_bfloat162(__float2bfloat16_rn(x - __bfloat162float(hx)),
                        __float2bfloat16_rn(y - __bfloat162float(hy)));
}
__device__ __forceinline__ uint32_t u32of(__nv_bfloat162 v) {
    return *reinterpret_cast<uint32_t*>(&v);
}

// ---------------------------------------------------------------------------
// wind strength
// ---------------------------------------------------------------------------
__global__ void wind_kernel(const float* __restrict__ u,
                            const float* __restrict__ v,
                            float* __restrict__ ws) {
    int t = blockIdx.x * blockDim.x + threadIdx.x;
    if (t >= B_ * N_) return;
    int b = t >> 10;
    int n = t & 1023;
    int r = n >> 5;
    int c = n & 31;
    const float* ub = u + b * 4096;
    const float* vb = v + b * 4096;
    float s = 0.0f;
#pragma unroll
    for (int dr = 0; dr < 2; ++dr)
#pragma unroll
        for (int dc = 0; dc < 2; ++dc) {
            int idx = (2 * r + dr) * 64 + (2 * c + dc);
            float uu = ub[idx], vv = vb[idx];
            s += sqrtf(uu * uu + vv * vv + 1e-8f);
        }
    ws[t] = s * 0.25f;
}

// ---------------------------------------------------------------------------
// bias precompute in MMA-fragment order.
// float4 index t encodes (b, qt, kt, w, nt, lane):
//   lane=t&31, nt=(t>>5)&7, w=(t>>8)&7, kt=(t>>11)&15, qt=(t>>15)&7, b=t>>18
// float4 = { bias(i0,j0), bias(i0,j0+1), bias(i0+8,j0), bias(i0+8,j0+1) }
//   with i0 = qt*128 + w*16 + (lane>>2), j0 = kt*64 + nt*8 + 2*(lane&3)
// ---------------------------------------------------------------------------
__device__ __forceinline__ float bias_val(float ei, float wi, float ej,
                                          float wj, float alpha, float beta) {
    float ed = fmaxf((ej - ei) * 1e-3f, 0.0f);
    float z = (wi + wj) * 0.5f - 5.0f;
    float wf = 1.0f / (1.0f + __expf(-z));
    float bia = -alpha * ed * (1.0f - beta * wf);
    return fminf(fmaxf(bia, -10.0f), 0.0f);
}

__global__ __launch_bounds__(256)
void bias_perm_kernel(const float* __restrict__ elev, const float* __restrict__ ws,
                      const float* __restrict__ alpha_p,
                      const float* __restrict__ beta_p,
                      float4* __restrict__ bias4) {
    const int t = blockIdx.x * blockDim.x + threadIdx.x;   // 0..2M-1
    const int lane = t & 31;
    const int nt = (t >> 5) & 7;
    const int w  = (t >> 8) & 7;
    const int kt = (t >> 11) & 15;
    const int qt = (t >> 15) & 7;
    const int b  = t >> 18;
    const float alpha = *alpha_p;
    const float beta = *beta_p;

    const int i0 = qt * 128 + w * 16 + (lane >> 2);
    const int j0 = kt * 64 + nt * 8 + 2 * (lane & 3);
    const float* e = elev + b * 1024;
    const float* wsb = ws + b * 1024;
    float ei0 = e[i0], ei1 = e[i0 + 8];
    float wi0 = wsb[i0], wi1 = wsb[i0 + 8];
    float ej0 = e[j0], ej1 = e[j0 + 1];
    float wj0 = wsb[j0], wj1 = wsb[j0 + 1];

    float4 o;
    o.x = bias_val(ei0, wi0, ej0, wj0, alpha, beta);
    o.y = bias_val(ei0, wi0, ej1, wj1, alpha, beta);
    o.z = bias_val(ei1, wi1, ej0, wj0, alpha, beta);
    o.w = bias_val(ei1, wi1, ej1, wj1, alpha, beta);
    bias4[t] = o;
}

// ---------------------------------------------------------------------------
// merged fp32 -> bf16 hi/lo split converter (x | wqkv | wproj)
// ---------------------------------------------------------------------------
#define N4_X (B_ * N_ * C_ / 4)          // 524288
#define N4_WQKV (3 * C_ * C_ / 4)        // 49152
#define N4_WPROJ (C_ * C_ / 4)           // 16384
#define N4_TOTAL (N4_X + N4_WQKV + N4_WPROJ)

__global__ void convert_all(const float* __restrict__ x,
                            const float* __restrict__ wqkv,
                            const float* __restrict__ wproj,
                            __nv_bfloat16* __restrict__ xh, __nv_bfloat16* __restrict__ xl,
                            __nv_bfloat16* __restrict__ wqh, __nv_bfloat16* __restrict__ wql,
                            __nv_bfloat16* __restrict__ wph, __nv_bfloat16* __restrict__ wpl) {
    int i = blockIdx.x * blockDim.x + threadIdx.x;
    const float* in;
    __nv_bfloat16 *hi, *lo;
    int off;
    if (i < N4_X) { in = x; hi = xh; lo = xl; off = i; }
    else if (i < N4_X + N4_WQKV) { in = wqkv; hi = wqh; lo = wql; off = i - N4_X; }
    else if (i < N4_TOTAL) { in = wproj; hi = wph; lo = wpl; off = i - N4_X - N4_WQKV; }
    else return;
    float4 v = reinterpret_cast<const float4*>(in)[off];
    __nv_bfloat162 h01, l01, h23, l23;
    split2(v.x, v.y, h01, l01);
    split2(v.z, v.w, h23, l23);
    uint2 hv = make_uint2(u32of(h01), u32of(h23));
    uint2 lv = make_uint2(u32of(l01), u32of(l23));
    *reinterpret_cast<uint2*>(hi + 4 * off) = hv;
    *reinterpret_cast<uint2*>(lo + 4 * off) = lv;
}

// ---------------------------------------------------------------------------
// bf16-split tensor-core GEMM, cp.async double-buffered (R7, proven).
// ---------------------------------------------------------------------------
#define PITCH 40
#define GEMM_BUF_BYTES (4 * 128 * PITCH * 2)
#define GEMM_SMEM_BYTES (2 * GEMM_BUF_BYTES)

template <bool HAS_BIAS, bool SPLIT_OUT>
__global__ __launch_bounds__(256, 2)
void gemm_bs(const __nv_bfloat16* __restrict__ Ah, const __nv_bfloat16* __restrict__ Al,
             const __nv_bfloat16* __restrict__ Bh, const __nv_bfloat16* __restrict__ Bl,
             const float* __restrict__ bias, float* __restrict__ C,
             __nv_bfloat16* __restrict__ Ch, __nv_bfloat16* __restrict__ Cl, int N) {
    extern __shared__ __align__(16) char smem_raw[];
    const uint32_t uS = smem_u32(smem_raw);

    const int tid = threadIdx.x;
    const int lane = tid & 31;
    const int wid = tid >> 5;
    const int wm = wid & 1;
    const int wn = wid >> 1;
    const int bx = blockIdx.x;
    const int by = blockIdx.y;

    const __nv_bfloat16* Agh = Ah + (size_t)by * 128 * 256;
    const __nv_bfloat16* Agl = Al + (size_t)by * 128 * 256;
    const __nv_bfloat16* Bgh = Bh + (size_t)bx * 128 * 256;
    const __nv_bfloat16* Bgl = Bl + (size_t)bx * 128 * 256;

    float acc[4][4][4];
#pragma unroll
    for (int mt = 0; mt < 4; ++mt)
#pragma unroll
        for (int nt = 0; nt < 4; ++nt)
#pragma unroll
            for (int i = 0; i < 4; ++i) acc[mt][nt][i] = 0.0f;

    const uint32_t aoff =
        (uint32_t)((wm * 64 + (lane & 15)) * PITCH + ((lane & 16) ? 8 : 0)) * 2;
    const uint32_t boff =
        (uint32_t)((wn * 32 + (lane & 7) + ((lane & 16) ? 8 : 0)) * PITCH +
                   ((lane & 8) ? 8 : 0)) * 2;

    const int row0 = tid >> 2;
    const int c8 = (tid & 3) * 8;

#pragma unroll
    for (int i = 0; i < 2; ++i) {
        int row = row0 + i * 64;
        size_t g = (size_t)row * 256 + c8;
        uint32_t so = (uint32_t)(row * PITCH + c8) * 2;
        CP_ASYNC16(uS + so, Agh + g);
        CP_ASYNC16(uS + 10240 + so, Agl + g);
        CP_ASYNC16(uS + 20480 + so, Bgh + g);
        CP_ASYNC16(uS + 30720 + so, Bgl + g);
    }
    CP_COMMIT();
    CP_WAIT0();
    __syncthreads();

#pragma unroll 1
    for (int kb = 0; kb < 8; ++kb) {
        const int p = kb & 1;
        const uint32_t bufb = uS + (uint32_t)p * GEMM_BUF_BYTES;

        if (kb < 7) {
            const uint32_t nb = uS + (uint32_t)(1 - p) * GEMM_BUF_BYTES;
#pragma unroll
            for (int i = 0; i < 2; ++i) {
                int row = row0 + i * 64;
                size_t g = (size_t)row * 256 + (kb + 1) * 32 + c8;
                uint32_t so = (uint32_t)(row * PITCH + c8) * 2;
                CP_ASYNC16(nb + so, Agh + g);
                CP_ASYNC16(nb + 10240 + so, Agl + g);
                CP_ASYNC16(nb + 20480 + so, Bgh + g);
                CP_ASYNC16(nb + 30720 + so, Bgl + g);
            }
            CP_COMMIT();
        }

        const uint32_t uAh = bufb, uAl = bufb + 10240;
        const uint32_t uBh = bufb + 20480, uBl = bufb + 30720;

#pragma unroll
        for (int kk = 0; kk < 2; ++kk) {
            const uint32_t kof = (uint32_t)(kk * 16) * 2;
            uint32_t bhf[2][4], blf[2][4];
#pragma unroll
            for (int ntp = 0; ntp < 2; ++ntp) {
                uint32_t ba = boff + (uint32_t)(ntp * 16 * PITCH) * 2 + kof;
                LDSM_X4(bhf[ntp][0], bhf[ntp][1], bhf[ntp][2], bhf[ntp][3], uBh + ba);
                LDSM_X4(blf[ntp][0], blf[ntp][1], blf[ntp][2], blf[ntp][3], uBl + ba);
            }
#pragma unroll
            for (int mt = 0; mt < 4; ++mt) {
                uint32_t aa = aoff + (uint32_t)(mt * 16 * PITCH) * 2 + kof;
                uint32_t ah0, ah1, ah2, ah3, al0, al1, al2, al3;
                LDSM_X4(ah0, ah1, ah2, ah3, uAh + aa);
                LDSM_X4(al0, al1, al2, al3, uAl + aa);
#pragma unroll
                for (int nt = 0; nt < 4; ++nt) {
                    const int ntp = nt >> 1;
                    const int hb = (nt & 1) * 2;
                    MMA_BF16(acc[mt][nt], ah0, ah1, ah2, ah3,
                             bhf[ntp][hb], bhf[ntp][hb + 1]);
                    MMA_BF16(acc[mt][nt], ah0, ah1, ah2, ah3,
                             blf[ntp][hb], blf[ntp][hb + 1]);
                    MMA_BF16(acc[mt][nt], al0, al1, al2, al3,
                             bhf[ntp][hb], bhf[ntp][hb + 1]);
                }
            }
        }

        if (kb < 7) CP_WAIT0();
        __syncthreads();
    }

    const int gid = lane >> 2;
    const int tig = lane & 3;
#pragma unroll
    for (int mt = 0; mt < 4; ++mt) {
        int row = by * 128 + wm * 64 + mt * 16 + gid;
#pragma unroll
        for (int nt = 0; nt < 4; ++nt) {
            int col = bx * 128 + wn * 32 + nt * 8 + 2 * tig;
            float2 v0 = make_float2(acc[mt][nt][0], acc[mt][nt][1]);
            float2 v1 = make_float2(acc[mt][nt][2], acc[mt][nt][3]);
            if (SPLIT_OUT) {
                __nv_bfloat162 h, l;
                split2(v0.x, v0.y, h, l);
                *reinterpret_cast<uint32_t*>(Ch + (size_t)row * N + col) = u32of(h);
                *reinterpret_cast<uint32_t*>(Cl + (size_t)row * N + col) = u32of(l);
                split2(v1.x, v1.y, h, l);
                *reinterpret_cast<uint32_t*>(Ch + (size_t)(row + 8) * N + col) = u32of(h);
                *reinterpret_cast<uint32_t*>(Cl + (size_t)(row + 8) * N + col) = u32of(l);
            } else {
                if (HAS_BIAS) {
                    float2 bb = *reinterpret_cast<const float2*>(bias + col);
                    v0.x += bb.x; v0.y += bb.y;
                    v1.x += bb.x; v1.y += bb.y;
                }
                *reinterpret_cast<float2*>(C + (size_t)row * N + col) = v0;
                *reinterpret_cast<float2*>(C + (size_t)(row + 8) * N + col) = v1;
            }
        }
    }
}

// ---------------------------------------------------------------------------
// tensor-core flash attention, cp.async double-buffered K/V,
// fragment-ordered bias (coalesced LDG.128).
// ---------------------------------------------------------------------------
#define ATTN_Q_BYTES (2 * 128 * PITCH * 2)
#define ATTN_BUF_BYTES (4 * 64 * PITCH * 2)
#define ATTN_SMEM_BYTES (ATTN_Q_BYTES + 2 * ATTN_BUF_BYTES)

__global__ __launch_bounds__(256, 2)
void attn_mma(const __nv_bfloat16* __restrict__ qkvh,
              const __nv_bfloat16* __restrict__ qkvl,
              const float4* __restrict__ bias4,
              __nv_bfloat16* __restrict__ outh,
              __nv_bfloat16* __restrict__ outl) {
    extern __shared__ __align__(16) char smem_raw[];
    __nv_bfloat16* Qh = reinterpret_cast<__nv_bfloat16*>(smem_raw);
    __nv_bfloat16* Ql = Qh + 128 * PITCH;
    const uint32_t uQh = smem_u32(Qh);
    const uint32_t uQl = uQh + 128 * PITCH * 2;
    const uint32_t uKV = uQl + 128 * PITCH * 2;

    const int tid = threadIdx.x;
    const int lane = tid & 31;
    const int w = tid >> 5;
    const int gid = lane >> 2;
    const int tig = lane & 3;
    const int qc = blockIdx.x;
    const int h  = blockIdx.y;
    const int b  = blockIdx.z;

    const float scale = 0.17677669529663687f;   // 1/sqrt(32)
    const int qrow0 = b * N_ + qc * 128;

    const int krow = tid >> 2;
    const int kc8 = (tid & 3) * 8;
    const uint32_t kso = (uint32_t)(krow * PITCH + kc8) * 2;

    // prologue: stage kt=0 into buffer 0
    {
        size_t g = (size_t)(b * N_ + krow) * 768 + 256 + h * HD_ + kc8;
        CP_ASYNC16(uKV + kso, qkvh + g);
        CP_ASYNC16(uKV + 5120 + kso, qkvl + g);
        CP_ASYNC16(uKV + 10240 + kso, qkvh + g + 256);
        CP_ASYNC16(uKV + 15360 + kso, qkvl + g + 256);
        CP_COMMIT();
    }

    // stage Q
#pragma unroll
    for (int i = 0; i < 2; ++i) {
        int slot = tid + i * 256;
        int row = slot >> 2;
        int c8 = (slot & 3) * 8;
        size_t g = (size_t)(qrow0 + row) * 768 + h * HD_ + c8;
        int so = row * PITCH + c8;
        *reinterpret_cast<uint4*>(&Qh[so]) =
            *reinterpret_cast<const uint4*>(qkvh + g);
        *reinterpret_cast<uint4*>(&Ql[so]) =
            *reinterpret_cast<const uint4*>(qkvl + g);
    }
    CP_WAIT0();
    __syncthreads();

    const uint32_t aoff =
        (uint32_t)((w * 16 + (lane & 15)) * PITCH + ((lane & 16) ? 8 : 0)) * 2;
    const uint32_t koff =
        (uint32_t)(((lane & 7) + ((lane & 16) ? 8 : 0)) * PITCH +
                   ((lane & 8) ? 8 : 0)) * 2;
    const uint32_t voff =
        (uint32_t)((lane & 15) * PITCH + ((lane & 16) ? 8 : 0)) * 2;

    // hoisted Q fragments
    uint32_t qh[2][4], ql[2][4];
#pragma unroll
    for (int kk = 0; kk < 2; ++kk) {
        const uint32_t kof = (uint32_t)(kk * 16) * 2;
        LDSM_X4(qh[kk][0], qh[kk][1], qh[kk][2], qh[kk][3], uQh + aoff + kof);
        LDSM_X4(ql[kk][0], ql[kk][1], ql[kk][2], ql[kk][3], uQl + aoff + kof);
    }

    float m0 = -1e30f, m1 = -1e30f, l0 = 0.0f, l1 = 0.0f;
    float oacc[4][4];
#pragma unroll
    for (int nt = 0; nt < 4; ++nt)
#pragma unroll
        for (int i = 0; i < 4; ++i) oacc[nt][i] = 0.0f;

    // fragment-ordered bias base: tile (b, qc, kt), then (w*8+nt)*32 + lane
    const float4* bias_tb =
        bias4 + ((size_t)((b * 8 + qc) * 16)) * 2048 + (w * 8) * 32 + lane;

#pragma unroll 1
    for (int kt = 0; kt < 16; ++kt) {
        const int p = kt & 1;
        const uint32_t bufb = uKV + (uint32_t)p * ATTN_BUF_BYTES;

        if (kt < 15) {
            const uint32_t nb = uKV + (uint32_t)(1 - p) * ATTN_BUF_BYTES;
            size_t g = (size_t)(b * N_ + (kt + 1) * 64 + krow) * 768 + 256 +
                       h * HD_ + kc8;
            CP_ASYNC16(nb + kso, qkvh + g);
            CP_ASYNC16(nb + 5120 + kso, qkvl + g);
            CP_ASYNC16(nb + 10240 + kso, qkvh + g + 256);
            CP_ASYNC16(nb + 15360 + kso, qkvl + g + 256);
            CP_COMMIT();
        }

        const uint32_t uKh = bufb, uKl = bufb + 5120;
        const uint32_t uVh = bufb + 10240, uVl = bufb + 15360;

        // ---- S = Q K^T (3-term split) ----
        float sacc[8][4];
#pragma unroll
        for (int nt = 0; nt < 8; ++nt)
#pragma unroll
            for (int i = 0; i < 4; ++i) sacc[nt][i] = 0.0f;

#pragma unroll
        for (int kk = 0; kk < 2; ++kk) {
            const uint32_t kof = (uint32_t)(kk * 16) * 2;
            uint32_t bh[4][4], bl[4][4];
#pragma unroll
            for (int ntp = 0; ntp < 4; ++ntp) {
                uint32_t ba = koff + (uint32_t)(ntp * 16 * PITCH) * 2 + kof;
                LDSM_X4(bh[ntp][0], bh[ntp][1], bh[ntp][2], bh[ntp][3], uKh + ba);
                LDSM_X4(bl[ntp][0], bl[ntp][1], bl[ntp][2], bl[ntp][3], uKl + ba);
            }
#pragma unroll
            for (int nt = 0; nt < 8; ++nt) {
                const int ntp = nt >> 1;
                const int hb = (nt & 1) * 2;
                MMA_BF16(sacc[nt], qh[kk][0], qh[kk][1], qh[kk][2], qh[kk][3],
                         bh[ntp][hb], bh[ntp][hb + 1]);
                MMA_BF16(sacc[nt], qh[kk][0], qh[kk][1], qh[kk][2], qh[kk][3],
                         bl[ntp][hb], bl[ntp][hb + 1]);
                MMA_BF16(sacc[nt], ql[kk][0], ql[kk][1], ql[kk][2], ql[kk][3],
                         bh[ntp][hb], bh[ntp][hb + 1]);
            }
        }

        // ---- scale + bias (fragment-ordered, coalesced LDG.128) ----
        const float4* bt = bias_tb + kt * 2048;
#pragma unroll
        for (int nt = 0; nt < 8; ++nt) {
            float4 bb = bt[nt * 32];
            sacc[nt][0] = fmaf(sacc[nt][0], scale, bb.x);
            sacc[nt][1] = fmaf(sacc[nt][1], scale, bb.y);
            sacc[nt][2] = fmaf(sacc[nt][2], scale, bb.z);
            sacc[nt][3] = fmaf(sacc[nt][3], scale, bb.w);
        }

        // ---- online softmax ----
        float mt0 = -1e30f, mt1 = -1e30f;
#pragma unroll
        for (int nt = 0; nt < 8; ++nt) {
            mt0 = fmaxf(mt0, fmaxf(sacc[nt][0], sacc[nt][1]));
            mt1 = fmaxf(mt1, fmaxf(sacc[nt][2], sacc[nt][3]));
        }
        mt0 = fmaxf(mt0, __shfl_xor_sync(0xffffffffu, mt0, 1));
        mt0 = fmaxf(mt0, __shfl_xor_sync(0xffffffffu, mt0, 2));
        mt1 = fmaxf(mt1, __shfl_xor_sync(0xffffffffu, mt1, 1));
        mt1 = fmaxf(mt1, __shfl_xor_sync(0xffffffffu, mt1, 2));
        float mn0 = fmaxf(m0, mt0), mn1 = fmaxf(m1, mt1);
        float sc0 = __expf(m0 - mn0), sc1 = __expf(m1 - mn1);
        float rs0 = 0.0f, rs1 = 0.0f;
#pragma unroll
        for (int nt = 0; nt < 8; ++nt) {
            sacc[nt][0] = __expf(sacc[nt][0] - mn0);
            sacc[nt][1] = __expf(sacc[nt][1] - mn0);
            sacc[nt][2] = __expf(sacc[nt][2] - mn1);
            sacc[nt][3] = __expf(sacc[nt][3] - mn1);
            rs0 += sacc[nt][0] + sacc[nt][1];
            rs1 += sacc[nt][2] + sacc[nt][3];
        }
        rs0 += __shfl_xor_sync(0xffffffffu, rs0, 1);
        rs0 += __shfl_xor_sync(0xffffffffu, rs0, 2);
        rs1 += __shfl_xor_sync(0xffffffffu, rs1, 1);
        rs1 += __shfl_xor_sync(0xffffffffu, rs1, 2);
        l0 = l0 * sc0 + rs0;
        l1 = l1 * sc1 + rs1;
        m0 = mn0; m1 = mn1;
#pragma unroll
        for (int nt = 0; nt < 4; ++nt) {
            oacc[nt][0] *= sc0; oacc[nt][1] *= sc0;
            oacc[nt][2] *= sc1; oacc[nt][3] *= sc1;
        }

        // ---- O += P V ----
#pragma unroll
        for (int ks = 0; ks < 4; ++ks) {
            __nv_bfloat162 hh, ll;
            uint32_t pah[4], pal[4];
            split2(sacc[2 * ks][0],     sacc[2 * ks][1],     hh, ll);
            pah[0] = u32of(hh); pal[0] = u32of(ll);
            split2(sacc[2 * ks][2],     sacc[2 * ks][3],     hh, ll);
            pah[1] = u32of(hh); pal[1] = u32of(ll);
            split2(sacc[2 * ks + 1][0], sacc[2 * ks + 1][1], hh, ll);
            pah[2] = u32of(hh); pal[2] = u32of(ll);
            split2(sacc[2 * ks + 1][2], sacc[2 * ks + 1][3], hh, ll);
            pah[3] = u32of(hh); pal[3] = u32of(ll);

            uint32_t vh[2][4], vl[2][4];
#pragma unroll
            for (int ntp = 0; ntp < 2; ++ntp) {
                uint32_t va = voff + (uint32_t)(ks * 16 * PITCH + ntp * 16) * 2;
                LDSM_X4T(vh[ntp][0], vh[ntp][1], vh[ntp][2], vh[ntp][3], uVh + va);
                LDSM_X4T(vl[ntp][0], vl[ntp][1], vl[ntp][2], vl[ntp][3], uVl + va);
            }
#pragma unroll
            for (int nt = 0; nt < 4; ++nt) {
                const int ntp = nt >> 1;
                const int hb = (nt & 1) * 2;
                MMA_BF16(oacc[nt], pah[0], pah[1], pah[2], pah[3],
                         vh[ntp][hb], vh[ntp][hb + 1]);
                MMA_BF16(oacc[nt], pah[0], pah[1], pah[2], pah[3],
                         vl[ntp][hb], vl[ntp][hb + 1]);
                MMA_BF16(oacc[nt], pal[0], pal[1], pal[2], pal[3],
                         vh[ntp][hb], vh[ntp][hb + 1]);
            }
        }

        if (kt < 15) CP_WAIT0();
        __syncthreads();
    }

    // ---- epilogue ----
    const float inv0 = 1.0f / l0;
    const float inv1 = 1.0f / l1;
    const int row0 = qrow0 + w * 16 + gid;
#pragma unroll
    for (int nt = 0; nt < 4; ++nt) {
        int col = h * HD_ + nt * 8 + 2 * tig;
        __nv_bfloat162 hv, lv;
        split2(oacc[nt][0] * inv0, oacc[nt][1] * inv0, hv, lv);
        *reinterpret_cast<uint32_t*>(outh + (size_t)row0 * C_ + col) = u32of(hv);
        *reinterpret_cast<uint32_t*>(outl + (size_t)row0 * C_ + col) = u32of(lv);
        split2(oacc[nt][2] * inv1, oacc[nt][3] * inv1, hv, lv);
        *reinterpret_cast<uint32_t*>(outh + (size_t)(row0 + 8) * C_ + col) = u32of(hv);
        *reinterpret_cast<uint32_t*>(outl + (size_t)(row0 + 8) * C_ + col) = u32of(lv);
    }
}

// ---------------------------------------------------------------------------
// launch
// ---------------------------------------------------------------------------
extern "C" void kernel_launch(void* const* d_in, const int* in_sizes, int n_in,
                              void* d_out, int out_size) {
    const float* x     = (const float*)d_in[0];
    const float* elev  = (const float*)d_in[1];
    const float* uw    = (const float*)d_in[2];
    const float* vw    = (const float*)d_in[3];
    const float* wqkv  = (const float*)d_in[4];
    const float* wproj = (const float*)d_in[5];
    const float* bproj = (const float*)d_in[6];
    const float* alpha = (const float*)d_in[7];
    const float* beta  = (const float*)d_in[8];
    float* out = (float*)d_out;

    float *ws_p;
    float4* bias4_p;
    __nv_bfloat16 *xh, *xl, *wqkvh, *wqkvl, *wprojh, *wprojl;
    __nv_bfloat16 *qkvh, *qkvl, *attnh, *attnl;
    cudaGetSymbolAddress((void**)&ws_p, g_ws);
    cudaGetSymbolAddress((void**)&bias4_p, g_bias4);
    cudaGetSymbolAddress((void**)&xh, g_xh);
    cudaGetSymbolAddress((void**)&xl, g_xl);
    cudaGetSymbolAddress((void**)&wqkvh, g_wqkvh);
    cudaGetSymbolAddress((void**)&wqkvl, g_wqkvl);
    cudaGetSymbolAddress((void**)&wprojh, g_wprojh);
    cudaGetSymbolAddress((void**)&wprojl, g_wprojl);
    cudaGetSymbolAddress((void**)&qkvh, g_qkvh);
    cudaGetSymbolAddress((void**)&qkvl, g_qkvl);
    cudaGetSymbolAddress((void**)&attnh, g_attnh);
    cudaGetSymbolAddress((void**)&attnl, g_attnl);

    cudaFuncSetAttribute(gemm_bs<false, true>,
                         cudaFuncAttributeMaxDynamicSharedMemorySize,
                         GEMM_SMEM_BYTES);
    cudaFuncSetAttribute(gemm_bs<true, false>,
                         cudaFuncAttributeMaxDynamicSharedMemorySize,
                         GEMM_SMEM_BYTES);
    cudaFuncSetAttribute(attn_mma,
                         cudaFuncAttributeMaxDynamicSharedMemorySize,
                         ATTN_SMEM_BYTES);

    // 1) wind strength, merged converts, fragment-ordered bias
    wind_kernel<<<32, 256>>>(uw, vw, ws_p);
    convert_all<<<(N4_TOTAL + 255) / 256, 256>>>(x, wqkv, wproj, xh, xl,
                                                 wqkvh, wqkvl, wprojh, wprojl);
    bias_perm_kernel<<<B_ * N_ * N_ / 4 / 256, 256>>>(elev, ws_p, alpha, beta,
                                                      bias4_p);

    // 2) qkv = x @ w_qkv^T (split output)
    gemm_bs<false, true><<<dim3(6, 64), 256, GEMM_SMEM_BYTES>>>(
        xh, xl, wqkvh, wqkvl, nullptr, nullptr, qkvh, qkvl, 768);

    // 3) flash attention (split output)
    attn_mma<<<dim3(8, NH_, B_), 256, ATTN_SMEM_BYTES>>>(
        qkvh, qkvl, bias4_p, attnh, attnl);

    // 4) out = attn @ w_proj^T + b_proj (f32 output)
    gemm_bs<true, false><<<dim3(2, 64), 256, GEMM_SMEM_BYTES>>>(
        attnh, attnl, wprojh, wprojl, bproj, out, nullptr, nullptr, 256);
}